// round 3
// baseline (speedup 1.0000x reference)
#include <cuda_runtime.h>
#include <math_constants.h>

#define NNODES 100000
#define NEDGES 1600000
#define EP     (NEDGES + NNODES)   // edges + self loops
#define HD     64
#define NCLS   10
#define NGRAPH 128

// ---------------- scratch (device globals; no allocations) ----------------
// 16B alignment REQUIRED: accessed with float4 loads/stores/atomics.
__device__ __align__(16) float g_hbuf[NNODES * HD];   // transformed features h = in @ W
__device__ __align__(16) float g_abuf[NNODES * HD];   // conv input / conv output
__device__ float g_als[NNODES];
__device__ float g_ald[NNODES];
__device__ float g_m[NNODES];
__device__ float g_den[NNODES];
__device__ float g_esc[EP];
__device__ int   g_src[EP];
__device__ int   g_dst[EP];

// ---------------- helpers ----------------
__device__ __forceinline__ void atomicMaxF(float* addr, float val) {
    if (val >= 0.f) atomicMax((int*)addr, __float_as_int(val));
    else            atomicMin((unsigned int*)addr, __float_as_uint(val));
}

__device__ __forceinline__ float eluf(float x) {
    return x > 0.f ? x : expm1f(x);
}

// ---------------- kernel 0: edge index copy (+ self loops) ----------------
// edge_index is INT32 (JAX x64 disabled downgrades jnp.int64 -> int32).
__global__ void k_build(const int* __restrict__ ei) {
    int i = blockIdx.x * blockDim.x + threadIdx.x;
    if (i < NEDGES) {
        g_src[i] = ei[i];
        g_dst[i] = ei[NEDGES + i];
    } else if (i < EP) {
        int n = i - NEDGES;
        g_src[i] = n;
        g_dst[i] = n;
    }
}

// ---------------- GEMM + attention coefs + init ---------------------------
// h = (elu?)(in) @ W ; als = h.a_s ; ald = h.a_d ; m=-inf; den=0; out-row = bias
// LAYER 0: reads xin param (raw x). LAYER 1: reads g_abuf with ELU applied.
// Block: 256 threads = 16 rows x 16 col-groups (4 cols each). Grid: N/16.
template <int LAYER>
__global__ __launch_bounds__(256) void k_gemm_attn(
    const float* __restrict__ xin,
    const float* __restrict__ W,
    const float* __restrict__ a_s,
    const float* __restrict__ a_d,
    const float* __restrict__ bias)
{
    __shared__ __align__(16) float Ws[64 * 68];
    __shared__ __align__(16) float xs[16 * 68];

    int t = threadIdx.x;
    for (int i = t; i < 64 * 64; i += 256)
        Ws[(i >> 6) * 68 + (i & 63)] = W[i];

    int r  = t >> 4;     // row within tile, 0..15
    int c  = t & 15;     // col group, 0..15
    int j0 = c * 4;

    float4 asv = *(const float4*)(a_s + j0);
    float4 adv = *(const float4*)(a_d + j0);
    float4 bv  = *(const float4*)(bias + j0);

    int base = blockIdx.x * 16;

    // load x tile (coalesced), ELU-on-load for layer 2
    for (int i = t; i < 16 * 64; i += 256) {
        int row = base + (i >> 6);
        int col = i & 63;
        float v;
        if (LAYER == 0) v = xin[row * 64 + col];
        else            v = eluf(g_abuf[row * 64 + col]);
        xs[(i >> 6) * 68 + col] = v;
    }
    __syncthreads();

    float4 acc = make_float4(0.f, 0.f, 0.f, 0.f);
    #pragma unroll
    for (int k = 0; k < 64; k++) {
        float xv = xs[r * 68 + k];
        float4 w = *(const float4*)&Ws[k * 68 + j0];
        acc.x += xv * w.x; acc.y += xv * w.y;
        acc.z += xv * w.z; acc.w += xv * w.w;
    }

    int node = base + r;
    *(float4*)&g_hbuf[node * 64 + j0] = acc;

    float ps = acc.x * asv.x + acc.y * asv.y + acc.z * asv.z + acc.w * asv.w;
    float pd = acc.x * adv.x + acc.y * adv.y + acc.z * adv.z + acc.w * adv.w;
    #pragma unroll
    for (int off = 8; off; off >>= 1) {
        ps += __shfl_xor_sync(0xffffffffu, ps, off);
        pd += __shfl_xor_sync(0xffffffffu, pd, off);
    }
    if (c == 0) {
        g_als[node] = ps;
        g_ald[node] = pd;
        g_m[node]   = -CUDART_INF_F;
        g_den[node] = 0.f;
    }
    // init conv output row to bias (scatter adds on top)
    *(float4*)&g_abuf[node * 64 + j0] = bv;
}

// ---------------- edge pass 1: score + segment max ------------------------
__global__ void k_edge1() {
    int e = blockIdx.x * blockDim.x + threadIdx.x;
    if (e >= EP) return;
    int s = g_src[e], d = g_dst[e];
    float sc = g_als[s] + g_ald[d];
    sc = sc > 0.f ? sc : 0.2f * sc;       // leaky relu, slope 0.2
    g_esc[e] = sc;
    atomicMaxF(&g_m[d], sc);
}

// ---------------- edge pass 2: exp + segment sum --------------------------
__global__ void k_edge2() {
    int e = blockIdx.x * blockDim.x + threadIdx.x;
    if (e >= EP) return;
    int d = g_dst[e];
    float ex = __expf(g_esc[e] - g_m[d]);
    g_esc[e] = ex;
    atomicAdd(&g_den[d], ex);
}

// ---------------- edge pass 3: weighted scatter (float4 atomics) ----------
// 16 lanes per edge; each lane handles 4 features via one float4 RED.
__global__ __launch_bounds__(256) void k_edge3() {
    int gid    = blockIdx.x * blockDim.x + threadIdx.x;
    int e      = gid >> 4;
    int lane16 = gid & 15;
    if (e >= EP) return;
    int   s = g_src[e], d = g_dst[e];
    float w = g_esc[e] / g_den[d];
    float4 hv = *(const float4*)&g_hbuf[s * 64 + lane16 * 4];
    float4 v  = make_float4(w * hv.x, w * hv.y, w * hv.z, w * hv.w);
    atomicAdd((float4*)&g_abuf[d * 64 + lane16 * 4], v);
}

// ---------------- zero the pooled output ----------------------------------
__global__ void k_zero(float* out) {
    int i = blockIdx.x * blockDim.x + threadIdx.x;
    if (i < NGRAPH * NCLS) out[i] = 0.f;
}

// ---------------- MLP head + global_add_pool ------------------------------
__global__ __launch_bounds__(256) void k_mlp_pool(
    const float* __restrict__ mw1, const float* __restrict__ mb1,
    const float* __restrict__ mw2, const float* __restrict__ mb2,
    const int* __restrict__ batch, float* __restrict__ out)
{
    __shared__ __align__(16) float W1s[64 * 68];
    __shared__ float W2s[64 * 12];
    __shared__ float b1s[64];
    __shared__ float b2s[NCLS];

    int t = threadIdx.x;
    for (int i = t; i < 64 * 64; i += 256)
        W1s[(i >> 6) * 68 + (i & 63)] = mw1[i];
    for (int i = t; i < 64 * NCLS; i += 256)
        W2s[(i / NCLS) * 12 + (i % NCLS)] = mw2[i];
    if (t < 64)   b1s[t] = mb1[t];
    if (t < NCLS) b2s[t] = mb2[t];
    __syncthreads();

    int node = blockIdx.x * blockDim.x + t;
    bool valid = node < NNODES;

    float z[64];
    #pragma unroll
    for (int j = 0; j < 64; j++) z[j] = 0.f;

    int b = 0;
    if (valid) {
        b = batch[node];
        #pragma unroll
        for (int k4 = 0; k4 < 16; k4++) {
            float4 xv4 = *(const float4*)&g_abuf[node * 64 + k4 * 4];
            float xv[4] = {xv4.x, xv4.y, xv4.z, xv4.w};
            #pragma unroll
            for (int kk = 0; kk < 4; kk++) {
                float xk = eluf(xv[kk]);
                int k = k4 * 4 + kk;
                #pragma unroll
                for (int j = 0; j < 64; j += 4) {
                    float4 w = *(const float4*)&W1s[k * 68 + j];
                    z[j]     += xk * w.x;
                    z[j + 1] += xk * w.y;
                    z[j + 2] += xk * w.z;
                    z[j + 3] += xk * w.w;
                }
            }
        }
    }

    float y[NCLS];
    #pragma unroll
    for (int c2 = 0; c2 < NCLS; c2++) y[c2] = valid ? b2s[c2] : 0.f;

    if (valid) {
        #pragma unroll
        for (int j = 0; j < 64; j++) {
            float zj = z[j] + b1s[j];
            zj = zj > 0.f ? zj : 0.f;
            #pragma unroll
            for (int c2 = 0; c2 < NCLS; c2++)
                y[c2] += zj * W2s[j * 12 + c2];
        }
    }

    // pool: warp-level pre-reduction when the whole warp shares one graph
    unsigned mask = 0xffffffffu;
    int b0 = __shfl_sync(mask, b, 0);
    bool uni = __all_sync(mask, valid && (b == b0));
    if (uni) {
        #pragma unroll
        for (int c2 = 0; c2 < NCLS; c2++) {
            float v = y[c2];
            #pragma unroll
            for (int off = 16; off; off >>= 1)
                v += __shfl_xor_sync(mask, v, off);
            if ((t & 31) == 0) atomicAdd(&out[b0 * NCLS + c2], v);
        }
    } else if (valid) {
        #pragma unroll
        for (int c2 = 0; c2 < NCLS; c2++)
            atomicAdd(&out[b * NCLS + c2], y[c2]);
    }
}

// ---------------- launch ---------------------------------------------------
extern "C" void kernel_launch(void* const* d_in, const int* in_sizes, int n_in,
                              void* d_out, int out_size) {
    const float* x     = (const float*)d_in[0];
    const int*   ei    = (const int*)d_in[1];     // int32 (JAX x64 disabled)
    const int*   batch = (const int*)d_in[2];     // int32
    const float* W1  = (const float*)d_in[3];
    const float* as1 = (const float*)d_in[4];
    const float* ad1 = (const float*)d_in[5];
    const float* b1  = (const float*)d_in[6];
    const float* W2  = (const float*)d_in[7];
    const float* as2 = (const float*)d_in[8];
    const float* ad2 = (const float*)d_in[9];
    const float* b2  = (const float*)d_in[10];
    const float* mw1 = (const float*)d_in[11];
    const float* mb1 = (const float*)d_in[12];
    const float* mw2 = (const float*)d_in[13];
    const float* mb2 = (const float*)d_in[14];
    float* out = (float*)d_out;

    const int TB = 256;
    int gridE  = (EP + TB - 1) / TB;
    long long tot3 = (long long)EP * 16;
    int gridE3 = (int)((tot3 + TB - 1) / TB);
    int gridG  = NNODES / 16;                 // 6250, exact
    int gridN  = (NNODES + TB - 1) / TB;

    k_build<<<gridE, TB>>>(ei);

    // conv 1
    k_gemm_attn<0><<<gridG, TB>>>(x, W1, as1, ad1, b1);
    k_edge1<<<gridE, TB>>>();
    k_edge2<<<gridE, TB>>>();
    k_edge3<<<gridE3, TB>>>();

    // conv 2 (reads g_abuf with ELU, rewrites g_abuf)
    k_gemm_attn<1><<<gridG, TB>>>(nullptr, W2, as2, ad2, b2);
    k_edge1<<<gridE, TB>>>();
    k_edge2<<<gridE, TB>>>();
    k_edge3<<<gridE3, TB>>>();

    // MLP + pool
    k_zero<<<(NGRAPH * NCLS + TB - 1) / TB, TB>>>(out);
    k_mlp_pool<<<gridN, TB>>>(mw1, mb1, mw2, mb2, batch, out);
}

// round 4
// speedup vs baseline: 1.3071x; 1.3071x over previous
#include <cuda_runtime.h>
#include <math_constants.h>

#define NNODES 100000
#define NEDGES 1600000
#define EP     (NEDGES + NNODES)   // edges + self loops
#define HD     64
#define NCLS   10
#define NGRAPH 128

#define SCHUNK 256
#define NBLK   ((NNODES + SCHUNK - 1) / SCHUNK)   // 391

// ---------------- scratch (device globals; no allocations) ----------------
__device__ __align__(16) float g_hbuf[NNODES * HD];   // h = in @ W
__device__ __align__(16) float g_abuf[NNODES * HD];   // conv input / output
__device__ float g_als[NNODES];
__device__ float g_ald[NNODES];
__device__ int   g_src[EP];
__device__ int   g_dst[EP];
__device__ int   g_deg[NNODES];
__device__ int   g_rowptr[NNODES + 1];
__device__ int   g_cursor[NNODES];
__device__ int   g_csr_src[EP];
__device__ int   g_partial[NBLK];
__device__ int   g_pscan[NBLK];

__device__ __forceinline__ float eluf(float x) {
    return x > 0.f ? x : expm1f(x);
}

// ---------------- CSR build ------------------------------------------------
__global__ void k_zero_deg() {
    int i = blockIdx.x * blockDim.x + threadIdx.x;
    if (i < NNODES) g_deg[i] = 0;
}

// edge_index is INT32 (JAX x64 disabled downgrades jnp.int64 -> int32)
__global__ void k_build(const int* __restrict__ ei) {
    int i = blockIdx.x * blockDim.x + threadIdx.x;
    if (i < NEDGES) {
        int s = ei[i], d = ei[NEDGES + i];
        g_src[i] = s;
        g_dst[i] = d;
        atomicAdd(&g_deg[d], 1);
    } else if (i < EP) {
        int n = i - NEDGES;
        g_src[i] = n;
        g_dst[i] = n;
        atomicAdd(&g_deg[n], 1);
    }
}

// block-level partial sums of deg
__global__ void k_scan1() {
    __shared__ int sh[SCHUNK];
    int t = threadIdx.x;
    int idx = blockIdx.x * SCHUNK + t;
    int v = (idx < NNODES) ? g_deg[idx] : 0;
    sh[t] = v;
    __syncthreads();
    for (int off = SCHUNK / 2; off; off >>= 1) {
        if (t < off) sh[t] += sh[t + off];
        __syncthreads();
    }
    if (t == 0) g_partial[blockIdx.x] = sh[0];
}

// exclusive scan of the 391 partials (single block, 512 threads)
__global__ void k_scan2() {
    __shared__ int sh[512];
    int t = threadIdx.x;
    int v = (t < NBLK) ? g_partial[t] : 0;
    sh[t] = v;
    __syncthreads();
    for (int off = 1; off < 512; off <<= 1) {
        int x = (t >= off) ? sh[t - off] : 0;
        __syncthreads();
        sh[t] += x;
        __syncthreads();
    }
    if (t < NBLK) g_pscan[t] = sh[t] - v;   // exclusive
}

// final rowptr + cursor
__global__ void k_scan3() {
    __shared__ int sh[SCHUNK];
    int t = threadIdx.x;
    int idx = blockIdx.x * SCHUNK + t;
    int v = (idx < NNODES) ? g_deg[idx] : 0;
    sh[t] = v;
    __syncthreads();
    for (int off = 1; off < SCHUNK; off <<= 1) {
        int x = (t >= off) ? sh[t - off] : 0;
        __syncthreads();
        sh[t] += x;
        __syncthreads();
    }
    int incl = sh[t];
    if (idx < NNODES) {
        int rp = g_pscan[blockIdx.x] + incl - v;   // exclusive
        g_rowptr[idx] = rp;
        g_cursor[idx] = rp;
        if (idx == NNODES - 1) g_rowptr[NNODES] = g_pscan[blockIdx.x] + incl; // == EP
    }
}

__global__ void k_scatter() {
    int e = blockIdx.x * blockDim.x + threadIdx.x;
    if (e >= EP) return;
    int d = g_dst[e];
    int pos = atomicAdd(&g_cursor[d], 1);
    g_csr_src[pos] = g_src[e];
}

// ---------------- GEMM + attention coefs -----------------------------------
// h = (elu?)(in) @ W ; als = h.a_s ; ald = h.a_d
// LAYER 0: reads xin (raw x). LAYER 1: reads g_abuf with ELU applied.
template <int LAYER>
__global__ __launch_bounds__(256) void k_gemm_attn(
    const float* __restrict__ xin,
    const float* __restrict__ W,
    const float* __restrict__ a_s,
    const float* __restrict__ a_d)
{
    __shared__ __align__(16) float Ws[64 * 68];
    __shared__ __align__(16) float xs[16 * 68];

    int t = threadIdx.x;
    for (int i = t; i < 64 * 64; i += 256)
        Ws[(i >> 6) * 68 + (i & 63)] = W[i];

    int r  = t >> 4;
    int c  = t & 15;
    int j0 = c * 4;

    float4 asv = *(const float4*)(a_s + j0);
    float4 adv = *(const float4*)(a_d + j0);

    int base = blockIdx.x * 16;

    for (int i = t; i < 16 * 64; i += 256) {
        int row = base + (i >> 6);
        int col = i & 63;
        float v;
        if (LAYER == 0) v = xin[row * 64 + col];
        else            v = eluf(g_abuf[row * 64 + col]);
        xs[(i >> 6) * 68 + col] = v;
    }
    __syncthreads();

    float4 acc = make_float4(0.f, 0.f, 0.f, 0.f);
    #pragma unroll
    for (int k = 0; k < 64; k++) {
        float xv = xs[r * 68 + k];
        float4 w = *(const float4*)&Ws[k * 68 + j0];
        acc.x += xv * w.x; acc.y += xv * w.y;
        acc.z += xv * w.z; acc.w += xv * w.w;
    }

    int node = base + r;
    *(float4*)&g_hbuf[node * 64 + j0] = acc;

    float ps = acc.x * asv.x + acc.y * asv.y + acc.z * asv.z + acc.w * asv.w;
    float pd = acc.x * adv.x + acc.y * adv.y + acc.z * adv.z + acc.w * adv.w;
    #pragma unroll
    for (int off = 8; off; off >>= 1) {
        ps += __shfl_xor_sync(0xffffffffu, ps, off);
        pd += __shfl_xor_sync(0xffffffffu, pd, off);
    }
    if (c == 0) {
        g_als[node] = ps;
        g_ald[node] = pd;
    }
}

// ---------------- fused conv: softmax + aggregate, warp per dst ------------
// out[d] = (sum_e ex_e * h[src_e]) / (sum_e ex_e) + bias   — no atomics.
__global__ __launch_bounds__(256) void k_conv(const float* __restrict__ bias) {
    int wid  = (blockIdx.x * 256 + threadIdx.x) >> 5;
    int lane = threadIdx.x & 31;
    if (wid >= NNODES) return;

    int r0 = g_rowptr[wid];
    int r1 = g_rowptr[wid + 1];
    float ald_d = g_ald[wid];

    // pass a: segment max (lanes stride over edges)
    float m = -CUDART_INF_F;
    for (int e = r0 + lane; e < r1; e += 32) {
        float sc = g_als[g_csr_src[e]] + ald_d;
        sc = sc > 0.f ? sc : 0.2f * sc;
        m = fmaxf(m, sc);
    }
    #pragma unroll
    for (int off = 16; off; off >>= 1)
        m = fmaxf(m, __shfl_xor_sync(0xffffffffu, m, off));

    // pass b: serial edge walk, coalesced h-row gather, register accumulate
    float den = 0.f, a0 = 0.f, a1 = 0.f;
    for (int e = r0; e < r1; e++) {
        int s = g_csr_src[e];                     // warp-uniform broadcast load
        float sc = g_als[s] + ald_d;
        sc = sc > 0.f ? sc : 0.2f * sc;
        float ex = __expf(sc - m);
        den += ex;
        a0 += ex * g_hbuf[s * 64 + lane];
        a1 += ex * g_hbuf[s * 64 + 32 + lane];
    }
    float inv = 1.f / den;
    g_abuf[wid * 64 + lane]      = a0 * inv + bias[lane];
    g_abuf[wid * 64 + 32 + lane] = a1 * inv + bias[lane + 32];
}

// ---------------- zero the pooled output ----------------------------------
__global__ void k_zero(float* out) {
    int i = blockIdx.x * blockDim.x + threadIdx.x;
    if (i < NGRAPH * NCLS) out[i] = 0.f;
}

// ---------------- MLP head + global_add_pool ------------------------------
__global__ __launch_bounds__(256) void k_mlp_pool(
    const float* __restrict__ mw1, const float* __restrict__ mb1,
    const float* __restrict__ mw2, const float* __restrict__ mb2,
    const int* __restrict__ batch, float* __restrict__ out)
{
    __shared__ __align__(16) float W1s[64 * 68];
    __shared__ float W2s[64 * 12];
    __shared__ float b1s[64];
    __shared__ float b2s[NCLS];

    int t = threadIdx.x;
    for (int i = t; i < 64 * 64; i += 256)
        W1s[(i >> 6) * 68 + (i & 63)] = mw1[i];
    for (int i = t; i < 64 * NCLS; i += 256)
        W2s[(i / NCLS) * 12 + (i % NCLS)] = mw2[i];
    if (t < 64)   b1s[t] = mb1[t];
    if (t < NCLS) b2s[t] = mb2[t];
    __syncthreads();

    int node = blockIdx.x * blockDim.x + t;
    bool valid = node < NNODES;

    float z[64];
    #pragma unroll
    for (int j = 0; j < 64; j++) z[j] = 0.f;

    int b = 0;
    if (valid) {
        b = batch[node];
        #pragma unroll
        for (int k4 = 0; k4 < 16; k4++) {
            float4 xv4 = *(const float4*)&g_abuf[node * 64 + k4 * 4];
            float xv[4] = {xv4.x, xv4.y, xv4.z, xv4.w};
            #pragma unroll
            for (int kk = 0; kk < 4; kk++) {
                float xk = eluf(xv[kk]);
                int k = k4 * 4 + kk;
                #pragma unroll
                for (int j = 0; j < 64; j += 4) {
                    float4 w = *(const float4*)&W1s[k * 68 + j];
                    z[j]     += xk * w.x;
                    z[j + 1] += xk * w.y;
                    z[j + 2] += xk * w.z;
                    z[j + 3] += xk * w.w;
                }
            }
        }
    }

    float y[NCLS];
    #pragma unroll
    for (int c2 = 0; c2 < NCLS; c2++) y[c2] = valid ? b2s[c2] : 0.f;

    if (valid) {
        #pragma unroll
        for (int j = 0; j < 64; j++) {
            float zj = z[j] + b1s[j];
            zj = zj > 0.f ? zj : 0.f;
            #pragma unroll
            for (int c2 = 0; c2 < NCLS; c2++)
                y[c2] += zj * W2s[j * 12 + c2];
        }
    }

    unsigned mask = 0xffffffffu;
    int b0 = __shfl_sync(mask, b, 0);
    bool uni = __all_sync(mask, valid && (b == b0));
    if (uni) {
        #pragma unroll
        for (int c2 = 0; c2 < NCLS; c2++) {
            float v = y[c2];
            #pragma unroll
            for (int off = 16; off; off >>= 1)
                v += __shfl_xor_sync(mask, v, off);
            if ((t & 31) == 0) atomicAdd(&out[b0 * NCLS + c2], v);
        }
    } else if (valid) {
        #pragma unroll
        for (int c2 = 0; c2 < NCLS; c2++)
            atomicAdd(&out[b * NCLS + c2], y[c2]);
    }
}

// ---------------- launch ---------------------------------------------------
extern "C" void kernel_launch(void* const* d_in, const int* in_sizes, int n_in,
                              void* d_out, int out_size) {
    const float* x     = (const float*)d_in[0];
    const int*   ei    = (const int*)d_in[1];     // int32
    const int*   batch = (const int*)d_in[2];     // int32
    const float* W1  = (const float*)d_in[3];
    const float* as1 = (const float*)d_in[4];
    const float* ad1 = (const float*)d_in[5];
    const float* b1  = (const float*)d_in[6];
    const float* W2  = (const float*)d_in[7];
    const float* as2 = (const float*)d_in[8];
    const float* ad2 = (const float*)d_in[9];
    const float* b2  = (const float*)d_in[10];
    const float* mw1 = (const float*)d_in[11];
    const float* mb1 = (const float*)d_in[12];
    const float* mw2 = (const float*)d_in[13];
    const float* mb2 = (const float*)d_in[14];
    float* out = (float*)d_out;

    const int TB = 256;
    int gridE = (EP + TB - 1) / TB;
    int gridN = (NNODES + TB - 1) / TB;
    int gridG = NNODES / 16;                  // 6250, exact
    int gridC = (NNODES * 32 + TB - 1) / TB;  // warp per node

    // CSR build (once, reused by both convs)
    k_zero_deg<<<gridN, TB>>>();
    k_build<<<gridE, TB>>>(ei);
    k_scan1<<<NBLK, SCHUNK>>>();
    k_scan2<<<1, 512>>>();
    k_scan3<<<NBLK, SCHUNK>>>();
    k_scatter<<<gridE, TB>>>();

    // conv 1
    k_gemm_attn<0><<<gridG, TB>>>(x, W1, as1, ad1);
    k_conv<<<gridC, TB>>>(b1);

    // conv 2
    k_gemm_attn<1><<<gridG, TB>>>(nullptr, W2, as2, ad2);
    k_conv<<<gridC, TB>>>(b2);

    // MLP + pool
    k_zero<<<(NGRAPH * NCLS + TB - 1) / TB, TB>>>(out);
    k_mlp_pool<<<gridN, TB>>>(mw1, mb1, mw2, mb2, batch, out);
}

// round 5
// speedup vs baseline: 1.3849x; 1.0595x over previous
#include <cuda_runtime.h>
#include <math_constants.h>

#define NNODES 100000
#define NEDGES 1600000
#define EP     (NEDGES + NNODES)   // edges + self loops
#define HD     64
#define NCLS   10
#define NGRAPH 128

#define SCHUNK 256
#define NBLK   ((NNODES + SCHUNK - 1) / SCHUNK)   // 391

// ---------------- scratch (device globals; no allocations) ----------------
__device__ __align__(16) float g_hbuf[NNODES * HD];   // h = in @ W
__device__ __align__(16) float g_abuf[NNODES * HD];   // conv input / output
__device__ float g_als[NNODES];
__device__ float g_ald[NNODES];
__device__ int   g_deg[NNODES];
__device__ int   g_rowptr[NNODES + 1];
__device__ int   g_cursor[NNODES];
__device__ int   g_csr_src[EP];
__device__ int   g_partial[NBLK];
__device__ int   g_pscan[NBLK];

__device__ __forceinline__ float eluf(float x) {
    return x > 0.f ? x : expm1f(x);
}

// ---------------- CSR build ------------------------------------------------
// deg starts at 1 (the self loop; it gets pre-placed at rowptr[n] in k_scan3)
__global__ void k_init_deg() {
    int i = blockIdx.x * blockDim.x + threadIdx.x;
    if (i < NNODES) g_deg[i] = 1;
}

// edge_index is INT32 (JAX x64 disabled downgrades jnp.int64 -> int32)
__global__ void k_deg(const int* __restrict__ ei) {
    int i = blockIdx.x * blockDim.x + threadIdx.x;
    if (i < NEDGES) atomicAdd(&g_deg[ei[NEDGES + i]], 1);
}

__global__ void k_scan1() {
    __shared__ int sh[SCHUNK];
    int t = threadIdx.x;
    int idx = blockIdx.x * SCHUNK + t;
    int v = (idx < NNODES) ? g_deg[idx] : 0;
    sh[t] = v;
    __syncthreads();
    for (int off = SCHUNK / 2; off; off >>= 1) {
        if (t < off) sh[t] += sh[t + off];
        __syncthreads();
    }
    if (t == 0) g_partial[blockIdx.x] = sh[0];
}

__global__ void k_scan2() {
    __shared__ int sh[512];
    int t = threadIdx.x;
    int v = (t < NBLK) ? g_partial[t] : 0;
    sh[t] = v;
    __syncthreads();
    for (int off = 1; off < 512; off <<= 1) {
        int x = (t >= off) ? sh[t - off] : 0;
        __syncthreads();
        sh[t] += x;
        __syncthreads();
    }
    if (t < NBLK) g_pscan[t] = sh[t] - v;   // exclusive
}

// rowptr + cursor + self-loop pre-placement
__global__ void k_scan3() {
    __shared__ int sh[SCHUNK];
    int t = threadIdx.x;
    int idx = blockIdx.x * SCHUNK + t;
    int v = (idx < NNODES) ? g_deg[idx] : 0;
    sh[t] = v;
    __syncthreads();
    for (int off = 1; off < SCHUNK; off <<= 1) {
        int x = (t >= off) ? sh[t - off] : 0;
        __syncthreads();
        sh[t] += x;
        __syncthreads();
    }
    int incl = sh[t];
    if (idx < NNODES) {
        int rp = g_pscan[blockIdx.x] + incl - v;   // exclusive
        g_rowptr[idx]  = rp;
        g_csr_src[rp]  = idx;        // self loop occupies slot 0 of the row
        g_cursor[idx]  = rp + 1;
        if (idx == NNODES - 1) g_rowptr[NNODES] = g_pscan[blockIdx.x] + incl; // == EP
    }
}

__global__ void k_scatter(const int* __restrict__ ei) {
    int e = blockIdx.x * blockDim.x + threadIdx.x;
    if (e >= NEDGES) return;
    int d = ei[NEDGES + e];
    int pos = atomicAdd(&g_cursor[d], 1);
    g_csr_src[pos] = ei[e];
}

// ---------------- GEMM + attention coefs -----------------------------------
template <int LAYER>
__global__ __launch_bounds__(256) void k_gemm_attn(
    const float* __restrict__ xin,
    const float* __restrict__ W,
    const float* __restrict__ a_s,
    const float* __restrict__ a_d)
{
    __shared__ __align__(16) float Ws[64 * 68];
    __shared__ __align__(16) float xs[16 * 68];

    int t = threadIdx.x;
    for (int i = t; i < 64 * 64; i += 256)
        Ws[(i >> 6) * 68 + (i & 63)] = W[i];

    int r  = t >> 4;
    int c  = t & 15;
    int j0 = c * 4;

    float4 asv = *(const float4*)(a_s + j0);
    float4 adv = *(const float4*)(a_d + j0);

    int base = blockIdx.x * 16;

    for (int i = t; i < 16 * 64; i += 256) {
        int row = base + (i >> 6);
        int col = i & 63;
        float v;
        if (LAYER == 0) v = xin[row * 64 + col];
        else            v = eluf(g_abuf[row * 64 + col]);
        xs[(i >> 6) * 68 + col] = v;
    }
    __syncthreads();

    float4 acc = make_float4(0.f, 0.f, 0.f, 0.f);
    #pragma unroll
    for (int k = 0; k < 64; k++) {
        float xv = xs[r * 68 + k];
        float4 w = *(const float4*)&Ws[k * 68 + j0];
        acc.x += xv * w.x; acc.y += xv * w.y;
        acc.z += xv * w.z; acc.w += xv * w.w;
    }

    int node = base + r;
    *(float4*)&g_hbuf[node * 64 + j0] = acc;

    float ps = acc.x * asv.x + acc.y * asv.y + acc.z * asv.z + acc.w * asv.w;
    float pd = acc.x * adv.x + acc.y * adv.y + acc.z * adv.z + acc.w * adv.w;
    #pragma unroll
    for (int off = 8; off; off >>= 1) {
        ps += __shfl_xor_sync(0xffffffffu, ps, off);
        pd += __shfl_xor_sync(0xffffffffu, pd, off);
    }
    if (c == 0) {
        g_als[node] = ps;
        g_ald[node] = pd;
    }
}

// ---------------- fused conv: softmax + aggregate, warp per dst ------------
// out[d] = (sum ex_e * h[src_e]) / (sum ex_e) + bias.
// Chunked lane-parallel scores; shuffle-broadcast into the gather loop, so
// the inner loop has NO dependent memory ops except the h-row gathers.
__global__ __launch_bounds__(256) void k_conv(const float* __restrict__ bias) {
    const unsigned FULL = 0xffffffffu;
    int wid  = (blockIdx.x * 256 + threadIdx.x) >> 5;
    int lane = threadIdx.x & 31;
    if (wid >= NNODES) return;

    int r0 = g_rowptr[wid];
    int r1 = g_rowptr[wid + 1];
    int deg = r1 - r0;
    float ald_d = g_ald[wid];

    // ---- chunk 0: coalesced src + score (kept for reuse) ----
    int e0 = r0 + lane;
    int   s_l  = 0;
    float sc_l = -CUDART_INF_F;
    if (e0 < r1) {
        s_l = g_csr_src[e0];
        float sc = g_als[s_l] + ald_d;
        sc_l = sc > 0.f ? sc : 0.2f * sc;
    }
    // ---- segment max over ALL edges ----
    float m = sc_l;
    for (int cb = r0 + 32; cb < r1; cb += 32) {
        int e = cb + lane;
        if (e < r1) {
            float sc = g_als[g_csr_src[e]] + ald_d;
            sc = sc > 0.f ? sc : 0.2f * sc;
            m = fmaxf(m, sc);
        }
    }
    #pragma unroll
    for (int off = 16; off; off >>= 1)
        m = fmaxf(m, __shfl_xor_sync(FULL, m, off));

    // ---- chunk 0 accumulate (reuses cached sc_l) ----
    float ex_l = (e0 < r1) ? __expf(sc_l - m) : 0.f;
    float denp = ex_l;
    float a0 = 0.f, a1 = 0.f;
    int cl = deg < 32 ? deg : 32;
    #pragma unroll 4
    for (int j = 0; j < cl; j++) {
        int   sj  = __shfl_sync(FULL, s_l, j);
        float exj = __shfl_sync(FULL, ex_l, j);
        a0 += exj * g_hbuf[sj * 64 + lane];
        a1 += exj * g_hbuf[sj * 64 + 32 + lane];
    }
    // ---- remaining chunks (deg > 32: rare, ~2% of nodes) ----
    for (int cb = r0 + 32; cb < r1; cb += 32) {
        int e = cb + lane;
        int   s  = 0;
        float ex = 0.f;
        if (e < r1) {
            s = g_csr_src[e];
            float sc = g_als[s] + ald_d;
            sc = sc > 0.f ? sc : 0.2f * sc;
            ex = __expf(sc - m);
        }
        denp += ex;
        int cl2 = (r1 - cb) < 32 ? (r1 - cb) : 32;
        #pragma unroll 4
        for (int j = 0; j < cl2; j++) {
            int   sj  = __shfl_sync(FULL, s, j);
            float exj = __shfl_sync(FULL, ex, j);
            a0 += exj * g_hbuf[sj * 64 + lane];
            a1 += exj * g_hbuf[sj * 64 + 32 + lane];
        }
    }

    // den: warp sum of lane partials
    float den = denp;
    #pragma unroll
    for (int off = 16; off; off >>= 1)
        den += __shfl_xor_sync(FULL, den, off);

    float inv = 1.f / den;
    g_abuf[wid * 64 + lane]      = a0 * inv + bias[lane];
    g_abuf[wid * 64 + 32 + lane] = a1 * inv + bias[lane + 32];
}

// ---------------- zero the pooled output ----------------------------------
__global__ void k_zero(float* out) {
    int i = blockIdx.x * blockDim.x + threadIdx.x;
    if (i < NGRAPH * NCLS) out[i] = 0.f;
}

// ---------------- MLP head + global_add_pool ------------------------------
__global__ __launch_bounds__(256) void k_mlp_pool(
    const float* __restrict__ mw1, const float* __restrict__ mb1,
    const float* __restrict__ mw2, const float* __restrict__ mb2,
    const int* __restrict__ batch, float* __restrict__ out)
{
    __shared__ __align__(16) float W1s[64 * 68];
    __shared__ float W2s[64 * 12];
    __shared__ float b1s[64];
    __shared__ float b2s[NCLS];

    int t = threadIdx.x;
    for (int i = t; i < 64 * 64; i += 256)
        W1s[(i >> 6) * 68 + (i & 63)] = mw1[i];
    for (int i = t; i < 64 * NCLS; i += 256)
        W2s[(i / NCLS) * 12 + (i % NCLS)] = mw2[i];
    if (t < 64)   b1s[t] = mb1[t];
    if (t < NCLS) b2s[t] = mb2[t];
    __syncthreads();

    int node = blockIdx.x * blockDim.x + t;
    bool valid = node < NNODES;

    float z[64];
    #pragma unroll
    for (int j = 0; j < 64; j++) z[j] = 0.f;

    int b = 0;
    if (valid) {
        b = batch[node];
        #pragma unroll
        for (int k4 = 0; k4 < 16; k4++) {
            float4 xv4 = *(const float4*)&g_abuf[node * 64 + k4 * 4];
            float xv[4] = {xv4.x, xv4.y, xv4.z, xv4.w};
            #pragma unroll
            for (int kk = 0; kk < 4; kk++) {
                float xk = eluf(xv[kk]);
                int k = k4 * 4 + kk;
                #pragma unroll
                for (int j = 0; j < 64; j += 4) {
                    float4 w = *(const float4*)&W1s[k * 68 + j];
                    z[j]     += xk * w.x;
                    z[j + 1] += xk * w.y;
                    z[j + 2] += xk * w.z;
                    z[j + 3] += xk * w.w;
                }
            }
        }
    }

    float y[NCLS];
    #pragma unroll
    for (int c2 = 0; c2 < NCLS; c2++) y[c2] = valid ? b2s[c2] : 0.f;

    if (valid) {
        #pragma unroll
        for (int j = 0; j < 64; j++) {
            float zj = z[j] + b1s[j];
            zj = zj > 0.f ? zj : 0.f;
            #pragma unroll
            for (int c2 = 0; c2 < NCLS; c2++)
                y[c2] += zj * W2s[j * 12 + c2];
        }
    }

    unsigned mask = 0xffffffffu;
    int b0 = __shfl_sync(mask, b, 0);
    bool uni = __all_sync(mask, valid && (b == b0));
    if (uni) {
        #pragma unroll
        for (int c2 = 0; c2 < NCLS; c2++) {
            float v = y[c2];
            #pragma unroll
            for (int off = 16; off; off >>= 1)
                v += __shfl_xor_sync(mask, v, off);
            if ((t & 31) == 0) atomicAdd(&out[b0 * NCLS + c2], v);
        }
    } else if (valid) {
        #pragma unroll
        for (int c2 = 0; c2 < NCLS; c2++)
            atomicAdd(&out[b * NCLS + c2], y[c2]);
    }
}

// ---------------- launch ---------------------------------------------------
extern "C" void kernel_launch(void* const* d_in, const int* in_sizes, int n_in,
                              void* d_out, int out_size) {
    const float* x     = (const float*)d_in[0];
    const int*   ei    = (const int*)d_in[1];     // int32
    const int*   batch = (const int*)d_in[2];     // int32
    const float* W1  = (const float*)d_in[3];
    const float* as1 = (const float*)d_in[4];
    const float* ad1 = (const float*)d_in[5];
    const float* b1  = (const float*)d_in[6];
    const float* W2  = (const float*)d_in[7];
    const float* as2 = (const float*)d_in[8];
    const float* ad2 = (const float*)d_in[9];
    const float* b2  = (const float*)d_in[10];
    const float* mw1 = (const float*)d_in[11];
    const float* mb1 = (const float*)d_in[12];
    const float* mw2 = (const float*)d_in[13];
    const float* mb2 = (const float*)d_in[14];
    float* out = (float*)d_out;

    const int TB = 256;
    int gridE = (NEDGES + TB - 1) / TB;
    int gridN = (NNODES + TB - 1) / TB;
    int gridG = NNODES / 16;                  // 6250, exact
    int gridC = (NNODES * 32 + TB - 1) / TB;  // warp per node

    // CSR build (once, reused by both convs)
    k_init_deg<<<gridN, TB>>>();
    k_deg<<<gridE, TB>>>(ei);
    k_scan1<<<NBLK, SCHUNK>>>();
    k_scan2<<<1, 512>>>();
    k_scan3<<<NBLK, SCHUNK>>>();
    k_scatter<<<gridE, TB>>>(ei);

    // conv 1
    k_gemm_attn<0><<<gridG, TB>>>(x, W1, as1, ad1);
    k_conv<<<gridC, TB>>>(b1);

    // conv 2
    k_gemm_attn<1><<<gridG, TB>>>(nullptr, W2, as2, ad2);
    k_conv<<<gridC, TB>>>(b2);

    // MLP + pool
    k_zero<<<(NGRAPH * NCLS + TB - 1) / TB, TB>>>(out);
    k_mlp_pool<<<gridN, TB>>>(mw1, mb1, mw2, mb2, batch, out);
}

// round 6
// speedup vs baseline: 1.4029x; 1.0130x over previous
#include <cuda_runtime.h>
#include <math_constants.h>

#define NNODES 100000
#define NEDGES 1600000
#define EP     (NEDGES + NNODES)   // edges + self loops
#define HD     64
#define NCLS   10
#define NGRAPH 128

#define SCHUNK 256
#define NBLK   ((NNODES + SCHUNK - 1) / SCHUNK)   // 391

// ---------------- scratch (device globals; no allocations) ----------------
__device__ __align__(16) float g_hbuf[NNODES * HD];   // h = in @ W
__device__ __align__(16) float g_abuf[NNODES * HD];   // conv input / output
__device__ float g_als[NNODES];
__device__ float g_ald[NNODES];
__device__ int   g_deg[NNODES];
__device__ int   g_rowptr[NNODES + 1];
__device__ int   g_cursor[NNODES];
__device__ int   g_csr_src[EP];
__device__ int   g_partial[NBLK];
__device__ int   g_pscan[NBLK];

__device__ __forceinline__ float eluf(float x) {
    return x > 0.f ? x : expm1f(x);
}

// ---------------- CSR build ------------------------------------------------
// deg starts at 1 (the self loop; pre-placed at rowptr[n] in k_scan3)
__global__ void k_init_deg() {
    int i = blockIdx.x * blockDim.x + threadIdx.x;
    if (i < NNODES) g_deg[i] = 1;
}

// edge_index is INT32 (JAX x64 disabled downgrades jnp.int64 -> int32)
__global__ void k_deg(const int* __restrict__ ei) {
    int i = blockIdx.x * blockDim.x + threadIdx.x;
    if (i < NEDGES) atomicAdd(&g_deg[ei[NEDGES + i]], 1);
}

__global__ void k_scan1() {
    __shared__ int sh[SCHUNK];
    int t = threadIdx.x;
    int idx = blockIdx.x * SCHUNK + t;
    int v = (idx < NNODES) ? g_deg[idx] : 0;
    sh[t] = v;
    __syncthreads();
    for (int off = SCHUNK / 2; off; off >>= 1) {
        if (t < off) sh[t] += sh[t + off];
        __syncthreads();
    }
    if (t == 0) g_partial[blockIdx.x] = sh[0];
}

__global__ void k_scan2() {
    __shared__ int sh[512];
    int t = threadIdx.x;
    int v = (t < NBLK) ? g_partial[t] : 0;
    sh[t] = v;
    __syncthreads();
    for (int off = 1; off < 512; off <<= 1) {
        int x = (t >= off) ? sh[t - off] : 0;
        __syncthreads();
        sh[t] += x;
        __syncthreads();
    }
    if (t < NBLK) g_pscan[t] = sh[t] - v;   // exclusive
}

// rowptr + cursor + self-loop pre-placement
__global__ void k_scan3() {
    __shared__ int sh[SCHUNK];
    int t = threadIdx.x;
    int idx = blockIdx.x * SCHUNK + t;
    int v = (idx < NNODES) ? g_deg[idx] : 0;
    sh[t] = v;
    __syncthreads();
    for (int off = 1; off < SCHUNK; off <<= 1) {
        int x = (t >= off) ? sh[t - off] : 0;
        __syncthreads();
        sh[t] += x;
        __syncthreads();
    }
    int incl = sh[t];
    if (idx < NNODES) {
        int rp = g_pscan[blockIdx.x] + incl - v;   // exclusive
        g_rowptr[idx]  = rp;
        g_csr_src[rp]  = idx;        // self loop occupies slot 0 of the row
        g_cursor[idx]  = rp + 1;
        if (idx == NNODES - 1) g_rowptr[NNODES] = g_pscan[blockIdx.x] + incl; // == EP
    }
}

__global__ void k_scatter(const int* __restrict__ ei) {
    int e = blockIdx.x * blockDim.x + threadIdx.x;
    if (e >= NEDGES) return;
    int d = ei[NEDGES + e];
    int pos = atomicAdd(&g_cursor[d], 1);
    g_csr_src[pos] = ei[e];
}

// ---------------- GEMM + attention coefs -----------------------------------
template <int LAYER>
__global__ __launch_bounds__(256) void k_gemm_attn(
    const float* __restrict__ xin,
    const float* __restrict__ W,
    const float* __restrict__ a_s,
    const float* __restrict__ a_d)
{
    __shared__ __align__(16) float Ws[64 * 68];
    __shared__ __align__(16) float xs[16 * 68];

    int t = threadIdx.x;
    for (int i = t; i < 64 * 64; i += 256)
        Ws[(i >> 6) * 68 + (i & 63)] = W[i];

    int r  = t >> 4;
    int c  = t & 15;
    int j0 = c * 4;

    float4 asv = *(const float4*)(a_s + j0);
    float4 adv = *(const float4*)(a_d + j0);

    int base = blockIdx.x * 16;

    for (int i = t; i < 16 * 64; i += 256) {
        int row = base + (i >> 6);
        int col = i & 63;
        float v;
        if (LAYER == 0) v = xin[row * 64 + col];
        else            v = eluf(g_abuf[row * 64 + col]);
        xs[(i >> 6) * 68 + col] = v;
    }
    __syncthreads();

    float4 acc = make_float4(0.f, 0.f, 0.f, 0.f);
    #pragma unroll
    for (int k = 0; k < 64; k++) {
        float xv = xs[r * 68 + k];
        float4 w = *(const float4*)&Ws[k * 68 + j0];
        acc.x += xv * w.x; acc.y += xv * w.y;
        acc.z += xv * w.z; acc.w += xv * w.w;
    }

    int node = base + r;
    *(float4*)&g_hbuf[node * 64 + j0] = acc;

    float ps = acc.x * asv.x + acc.y * asv.y + acc.z * asv.z + acc.w * asv.w;
    float pd = acc.x * adv.x + acc.y * adv.y + acc.z * adv.z + acc.w * adv.w;
    #pragma unroll
    for (int off = 8; off; off >>= 1) {
        ps += __shfl_xor_sync(0xffffffffu, ps, off);
        pd += __shfl_xor_sync(0xffffffffu, pd, off);
    }
    if (c == 0) {
        g_als[node] = ps;
        g_ald[node] = pd;
    }
}

// ---------------- fused conv: shift-free softmax + aggregate ---------------
// out[d] = (sum ex_e * h[src_e]) / (sum ex_e) + bias.
// Softmax is shift-invariant; scores here are O(10) so exp() cannot overflow
// (clamped at 75 as a hard safety net). Single streaming loop:
// coalesced src + lane-parallel exp, shuffle-broadcast, float2 row gather.
__global__ __launch_bounds__(256) void k_conv(const float* __restrict__ bias) {
    const unsigned FULL = 0xffffffffu;
    int wid  = (blockIdx.x * 256 + threadIdx.x) >> 5;
    int lane = threadIdx.x & 31;
    if (wid >= NNODES) return;

    int r0 = g_rowptr[wid];
    int r1 = g_rowptr[wid + 1];
    float ald_d = g_ald[wid];

    float ax = 0.f, ay = 0.f;
    float denp = 0.f;

    for (int cb = r0; cb < r1; cb += 32) {
        int e = cb + lane;
        int   s  = 0;
        float ex = 0.f;
        if (e < r1) {
            s = g_csr_src[e];
            float sc = g_als[s] + ald_d;
            sc = sc > 0.f ? sc : 0.2f * sc;       // leaky relu
            ex = __expf(fminf(sc, 75.f));
        }
        denp += ex;
        int cl = (r1 - cb) < 32 ? (r1 - cb) : 32;
        #pragma unroll 8
        for (int j = 0; j < cl; j++) {
            int   sj  = __shfl_sync(FULL, s, j);
            float exj = __shfl_sync(FULL, ex, j);
            float2 hv = *(const float2*)&g_hbuf[sj * 64 + lane * 2];
            ax += exj * hv.x;
            ay += exj * hv.y;
        }
    }

    float den = denp;
    #pragma unroll
    for (int off = 16; off; off >>= 1)
        den += __shfl_xor_sync(FULL, den, off);

    float inv = 1.f / den;
    float2 o;
    o.x = ax * inv + bias[lane * 2];
    o.y = ay * inv + bias[lane * 2 + 1];
    *(float2*)&g_abuf[wid * 64 + lane * 2] = o;
}

// ---------------- zero the pooled output ----------------------------------
__global__ void k_zero(float* out) {
    int i = blockIdx.x * blockDim.x + threadIdx.x;
    if (i < NGRAPH * NCLS) out[i] = 0.f;
}

// ---------------- MLP head + global_add_pool ------------------------------
__global__ __launch_bounds__(256) void k_mlp_pool(
    const float* __restrict__ mw1, const float* __restrict__ mb1,
    const float* __restrict__ mw2, const float* __restrict__ mb2,
    const int* __restrict__ batch, float* __restrict__ out)
{
    __shared__ __align__(16) float W1s[64 * 68];
    __shared__ float W2s[64 * 12];
    __shared__ float b1s[64];
    __shared__ float b2s[NCLS];

    int t = threadIdx.x;
    for (int i = t; i < 64 * 64; i += 256)
        W1s[(i >> 6) * 68 + (i & 63)] = mw1[i];
    for (int i = t; i < 64 * NCLS; i += 256)
        W2s[(i / NCLS) * 12 + (i % NCLS)] = mw2[i];
    if (t < 64)   b1s[t] = mb1[t];
    if (t < NCLS) b2s[t] = mb2[t];
    __syncthreads();

    int node = blockIdx.x * blockDim.x + t;
    bool valid = node < NNODES;

    float z[64];
    #pragma unroll
    for (int j = 0; j < 64; j++) z[j] = 0.f;

    int b = 0;
    if (valid) {
        b = batch[node];
        #pragma unroll
        for (int k4 = 0; k4 < 16; k4++) {
            float4 xv4 = *(const float4*)&g_abuf[node * 64 + k4 * 4];
            float xv[4] = {xv4.x, xv4.y, xv4.z, xv4.w};
            #pragma unroll
            for (int kk = 0; kk < 4; kk++) {
                float xk = eluf(xv[kk]);
                int k = k4 * 4 + kk;
                #pragma unroll
                for (int j = 0; j < 64; j += 4) {
                    float4 w = *(const float4*)&W1s[k * 68 + j];
                    z[j]     += xk * w.x;
                    z[j + 1] += xk * w.y;
                    z[j + 2] += xk * w.z;
                    z[j + 3] += xk * w.w;
                }
            }
        }
    }

    float y[NCLS];
    #pragma unroll
    for (int c2 = 0; c2 < NCLS; c2++) y[c2] = valid ? b2s[c2] : 0.f;

    if (valid) {
        #pragma unroll
        for (int j = 0; j < 64; j++) {
            float zj = z[j] + b1s[j];
            zj = zj > 0.f ? zj : 0.f;
            #pragma unroll
            for (int c2 = 0; c2 < NCLS; c2++)
                y[c2] += zj * W2s[j * 12 + c2];
        }
    }

    unsigned mask = 0xffffffffu;
    int b0 = __shfl_sync(mask, b, 0);
    bool uni = __all_sync(mask, valid && (b == b0));
    if (uni) {
        #pragma unroll
        for (int c2 = 0; c2 < NCLS; c2++) {
            float v = y[c2];
            #pragma unroll
            for (int off = 16; off; off >>= 1)
                v += __shfl_xor_sync(mask, v, off);
            if ((t & 31) == 0) atomicAdd(&out[b0 * NCLS + c2], v);
        }
    } else if (valid) {
        #pragma unroll
        for (int c2 = 0; c2 < NCLS; c2++)
            atomicAdd(&out[b * NCLS + c2], y[c2]);
    }
}

// ---------------- launch ---------------------------------------------------
extern "C" void kernel_launch(void* const* d_in, const int* in_sizes, int n_in,
                              void* d_out, int out_size) {
    const float* x     = (const float*)d_in[0];
    const int*   ei    = (const int*)d_in[1];     // int32
    const int*   batch = (const int*)d_in[2];     // int32
    const float* W1  = (const float*)d_in[3];
    const float* as1 = (const float*)d_in[4];
    const float* ad1 = (const float*)d_in[5];
    const float* b1  = (const float*)d_in[6];
    const float* W2  = (const float*)d_in[7];
    const float* as2 = (const float*)d_in[8];
    const float* ad2 = (const float*)d_in[9];
    const float* b2  = (const float*)d_in[10];
    const float* mw1 = (const float*)d_in[11];
    const float* mb1 = (const float*)d_in[12];
    const float* mw2 = (const float*)d_in[13];
    const float* mb2 = (const float*)d_in[14];
    float* out = (float*)d_out;

    const int TB = 256;
    int gridE = (NEDGES + TB - 1) / TB;
    int gridN = (NNODES + TB - 1) / TB;
    int gridG = NNODES / 16;                  // 6250, exact
    int gridC = (NNODES * 32 + TB - 1) / TB;  // warp per node

    // CSR build (once, reused by both convs)
    k_init_deg<<<gridN, TB>>>();
    k_deg<<<gridE, TB>>>(ei);
    k_scan1<<<NBLK, SCHUNK>>>();
    k_scan2<<<1, 512>>>();
    k_scan3<<<NBLK, SCHUNK>>>();
    k_scatter<<<gridE, TB>>>(ei);

    // conv 1
    k_gemm_attn<0><<<gridG, TB>>>(x, W1, as1, ad1);
    k_conv<<<gridC, TB>>>(b1);

    // conv 2
    k_gemm_attn<1><<<gridG, TB>>>(nullptr, W2, as2, ad2);
    k_conv<<<gridC, TB>>>(b2);

    // MLP + pool
    k_zero<<<(NGRAPH * NCLS + TB - 1) / TB, TB>>>(out);
    k_mlp_pool<<<gridN, TB>>>(mw1, mb1, mw2, mb2, batch, out);
}

// round 7
// speedup vs baseline: 1.7839x; 1.2716x over previous
#include <cuda_runtime.h>
#include <math_constants.h>

#define NNODES 100000
#define NEDGES 1600000
#define EP     (NEDGES + NNODES)   // edges + self loops
#define HD     64
#define NCLS   10
#define NGRAPH 128

#define SCHUNK 256
#define NBLK   ((NNODES + SCHUNK - 1) / SCHUNK)   // 391

// ---------------- scratch (device globals; no allocations) ----------------
__device__ __align__(16) float g_hbuf[NNODES * HD];   // h = in @ W
__device__ __align__(16) float g_abuf[NNODES * HD];   // conv input / output
__device__ float g_als[NNODES];
__device__ float g_ald[NNODES];
__device__ int   g_deg[NNODES];
__device__ int   g_rowptr[NNODES + 1];
__device__ int   g_cursor[NNODES];
__device__ int   g_csr_src[EP];
__device__ int   g_partial[NBLK];
__device__ int   g_pscan[NBLK];

__device__ __forceinline__ float eluf(float x) {
    return x > 0.f ? x : expm1f(x);
}

// ---------------- CSR build ------------------------------------------------
__global__ void k_init_deg() {
    int i = blockIdx.x * blockDim.x + threadIdx.x;
    if (i < NNODES) g_deg[i] = 1;      // self loop counted up front
}

// edge_index is INT32 (JAX x64 disabled downgrades jnp.int64 -> int32)
__global__ void k_deg(const int* __restrict__ ei) {
    int i = blockIdx.x * blockDim.x + threadIdx.x;
    if (i < NEDGES) atomicAdd(&g_deg[ei[NEDGES + i]], 1);
}

__global__ void k_scan1() {
    __shared__ int sh[SCHUNK];
    int t = threadIdx.x;
    int idx = blockIdx.x * SCHUNK + t;
    int v = (idx < NNODES) ? g_deg[idx] : 0;
    sh[t] = v;
    __syncthreads();
    for (int off = SCHUNK / 2; off; off >>= 1) {
        if (t < off) sh[t] += sh[t + off];
        __syncthreads();
    }
    if (t == 0) g_partial[blockIdx.x] = sh[0];
}

__global__ void k_scan2() {
    __shared__ int sh[512];
    int t = threadIdx.x;
    int v = (t < NBLK) ? g_partial[t] : 0;
    sh[t] = v;
    __syncthreads();
    for (int off = 1; off < 512; off <<= 1) {
        int x = (t >= off) ? sh[t - off] : 0;
        __syncthreads();
        sh[t] += x;
        __syncthreads();
    }
    if (t < NBLK) g_pscan[t] = sh[t] - v;   // exclusive
}

// rowptr + cursor + self-loop pre-placement
__global__ void k_scan3() {
    __shared__ int sh[SCHUNK];
    int t = threadIdx.x;
    int idx = blockIdx.x * SCHUNK + t;
    int v = (idx < NNODES) ? g_deg[idx] : 0;
    sh[t] = v;
    __syncthreads();
    for (int off = 1; off < SCHUNK; off <<= 1) {
        int x = (t >= off) ? sh[t - off] : 0;
        __syncthreads();
        sh[t] += x;
        __syncthreads();
    }
    int incl = sh[t];
    if (idx < NNODES) {
        int rp = g_pscan[blockIdx.x] + incl - v;   // exclusive
        g_rowptr[idx]  = rp;
        g_csr_src[rp]  = idx;        // self loop occupies slot 0 of the row
        g_cursor[idx]  = rp + 1;
        if (idx == NNODES - 1) g_rowptr[NNODES] = g_pscan[blockIdx.x] + incl; // == EP
    }
}

__global__ void k_scatter(const int* __restrict__ ei) {
    int e = blockIdx.x * blockDim.x + threadIdx.x;
    if (e >= NEDGES) return;
    int d = ei[NEDGES + e];
    int pos = atomicAdd(&g_cursor[d], 1);
    g_csr_src[pos] = ei[e];
}

// ---------------- GEMM + attention coefs (register-blocked 4x4) ------------
// 64 rows / block, 256 threads: thread (rq = t>>4, c = t&15) computes rows
// rq*4..rq*4+3 x cols c*4..c*4+3. Per k-step: 1 LDS.128 (W) + 4 broadcast
// LDS (x) feed 16 FFMA -> FFMA-issue-bound, not smem-bound.
template <int LAYER>
__global__ __launch_bounds__(256) void k_gemm_attn(
    const float* __restrict__ xin,
    const float* __restrict__ W,
    const float* __restrict__ a_s,
    const float* __restrict__ a_d)
{
    __shared__ __align__(16) float Ws[64 * 68];
    __shared__ __align__(16) float xs[64 * 68];

    int t = threadIdx.x;
    int base = blockIdx.x * 64;

    // load W (64x64) as float4, padded stride 68
    for (int i = t; i < 1024; i += 256) {
        float4 w = *(const float4*)(W + i * 4);
        *(float4*)&Ws[(i >> 4) * 68 + (i & 15) * 4] = w;
    }
    // load x tile (64x64) as float4; ELU-on-load for layer 2; OOB rows -> 0
    for (int i = t; i < 1024; i += 256) {
        int row = i >> 4, c4 = i & 15;
        int grow = base + row;
        float4 v = make_float4(0.f, 0.f, 0.f, 0.f);
        if (grow < NNODES) {
            if (LAYER == 0) {
                v = *(const float4*)(xin + grow * 64 + c4 * 4);
            } else {
                float4 u = *(const float4*)&g_abuf[grow * 64 + c4 * 4];
                v = make_float4(eluf(u.x), eluf(u.y), eluf(u.z), eluf(u.w));
            }
        }
        *(float4*)&xs[row * 68 + c4 * 4] = v;
    }
    __syncthreads();

    int c  = t & 15;
    int rq = t >> 4;
    int j0 = c * 4;
    int rbase = rq * 4;

    float4 acc0 = make_float4(0.f,0.f,0.f,0.f);
    float4 acc1 = acc0, acc2 = acc0, acc3 = acc0;

    #pragma unroll 8
    for (int k = 0; k < 64; k++) {
        float4 w  = *(const float4*)&Ws[k * 68 + j0];
        float x0 = xs[(rbase + 0) * 68 + k];
        float x1 = xs[(rbase + 1) * 68 + k];
        float x2 = xs[(rbase + 2) * 68 + k];
        float x3 = xs[(rbase + 3) * 68 + k];
        acc0.x += x0 * w.x; acc0.y += x0 * w.y; acc0.z += x0 * w.z; acc0.w += x0 * w.w;
        acc1.x += x1 * w.x; acc1.y += x1 * w.y; acc1.z += x1 * w.z; acc1.w += x1 * w.w;
        acc2.x += x2 * w.x; acc2.y += x2 * w.y; acc2.z += x2 * w.z; acc2.w += x2 * w.w;
        acc3.x += x3 * w.x; acc3.y += x3 * w.y; acc3.z += x3 * w.z; acc3.w += x3 * w.w;
    }

    float4 asv = *(const float4*)(a_s + j0);
    float4 adv = *(const float4*)(a_d + j0);

    float4 accs[4] = {acc0, acc1, acc2, acc3};
    #pragma unroll
    for (int i = 0; i < 4; i++) {
        int row = base + rbase + i;
        float4 a = accs[i];
        if (row < NNODES)
            *(float4*)&g_hbuf[row * 64 + j0] = a;
        float ps = a.x * asv.x + a.y * asv.y + a.z * asv.z + a.w * asv.w;
        float pd = a.x * adv.x + a.y * adv.y + a.z * adv.z + a.w * adv.w;
        // reduce across the 16 c-lanes (xor offsets 1..8 stay in the half-warp)
        #pragma unroll
        for (int off = 8; off; off >>= 1) {
            ps += __shfl_xor_sync(0xffffffffu, ps, off);
            pd += __shfl_xor_sync(0xffffffffu, pd, off);
        }
        if (c == 0 && row < NNODES) {
            g_als[row] = ps;
            g_ald[row] = pd;
        }
    }
}

// ---------------- fused conv: shift-free softmax + aggregate ---------------
// out[d] = (sum ex_e * h[src_e]) / (sum ex_e) + bias.  Scores are O(10) so
// exp() cannot overflow (clamped at 75 as a hard safety net).
__global__ __launch_bounds__(256) void k_conv(const float* __restrict__ bias) {
    const unsigned FULL = 0xffffffffu;
    int wid  = (blockIdx.x * 256 + threadIdx.x) >> 5;
    int lane = threadIdx.x & 31;
    if (wid >= NNODES) return;

    int r0 = g_rowptr[wid];
    int r1 = g_rowptr[wid + 1];
    float ald_d = g_ald[wid];

    float ax = 0.f, ay = 0.f;
    float denp = 0.f;

    for (int cb = r0; cb < r1; cb += 32) {
        int e = cb + lane;
        int   s  = 0;
        float ex = 0.f;
        if (e < r1) {
            s = g_csr_src[e];
            float sc = g_als[s] + ald_d;
            sc = sc > 0.f ? sc : 0.2f * sc;       // leaky relu
            ex = __expf(fminf(sc, 75.f));
        }
        denp += ex;
        int cl = (r1 - cb) < 32 ? (r1 - cb) : 32;
        #pragma unroll 8
        for (int j = 0; j < cl; j++) {
            int   sj  = __shfl_sync(FULL, s, j);
            float exj = __shfl_sync(FULL, ex, j);
            float2 hv = *(const float2*)&g_hbuf[sj * 64 + lane * 2];
            ax += exj * hv.x;
            ay += exj * hv.y;
        }
    }

    float den = denp;
    #pragma unroll
    for (int off = 16; off; off >>= 1)
        den += __shfl_xor_sync(FULL, den, off);

    float inv = 1.f / den;
    float2 o;
    o.x = ax * inv + bias[lane * 2];
    o.y = ay * inv + bias[lane * 2 + 1];
    *(float2*)&g_abuf[wid * 64 + lane * 2] = o;
}

// ---------------- zero the pooled output ----------------------------------
__global__ void k_zero(float* out) {
    int i = blockIdx.x * blockDim.x + threadIdx.x;
    if (i < NGRAPH * NCLS) out[i] = 0.f;
}

// ---------------- MLP head + global_add_pool ------------------------------
__global__ __launch_bounds__(256) void k_mlp_pool(
    const float* __restrict__ mw1, const float* __restrict__ mb1,
    const float* __restrict__ mw2, const float* __restrict__ mb2,
    const int* __restrict__ batch, float* __restrict__ out)
{
    __shared__ __align__(16) float W1s[64 * 68];
    __shared__ float W2s[64 * 12];
    __shared__ float b1s[64];
    __shared__ float b2s[NCLS];

    int t = threadIdx.x;
    for (int i = t; i < 64 * 64; i += 256)
        W1s[(i >> 6) * 68 + (i & 63)] = mw1[i];
    for (int i = t; i < 64 * NCLS; i += 256)
        W2s[(i / NCLS) * 12 + (i % NCLS)] = mw2[i];
    if (t < 64)   b1s[t] = mb1[t];
    if (t < NCLS) b2s[t] = mb2[t];
    __syncthreads();

    int node = blockIdx.x * blockDim.x + t;
    bool valid = node < NNODES;

    float z[64];
    #pragma unroll
    for (int j = 0; j < 64; j++) z[j] = 0.f;

    int b = 0;
    if (valid) {
        b = batch[node];
        #pragma unroll
        for (int k4 = 0; k4 < 16; k4++) {
            float4 xv4 = *(const float4*)&g_abuf[node * 64 + k4 * 4];
            float xv[4] = {xv4.x, xv4.y, xv4.z, xv4.w};
            #pragma unroll
            for (int kk = 0; kk < 4; kk++) {
                float xk = eluf(xv[kk]);
                int k = k4 * 4 + kk;
                #pragma unroll
                for (int j = 0; j < 64; j += 4) {
                    float4 w = *(const float4*)&W1s[k * 68 + j];
                    z[j]     += xk * w.x;
                    z[j + 1] += xk * w.y;
                    z[j + 2] += xk * w.z;
                    z[j + 3] += xk * w.w;
                }
            }
        }
    }

    float y[NCLS];
    #pragma unroll
    for (int c2 = 0; c2 < NCLS; c2++) y[c2] = valid ? b2s[c2] : 0.f;

    if (valid) {
        #pragma unroll
        for (int j = 0; j < 64; j++) {
            float zj = z[j] + b1s[j];
            zj = zj > 0.f ? zj : 0.f;
            #pragma unroll
            for (int c2 = 0; c2 < NCLS; c2++)
                y[c2] += zj * W2s[j * 12 + c2];
        }
    }

    unsigned mask = 0xffffffffu;
    int b0 = __shfl_sync(mask, b, 0);
    bool uni = __all_sync(mask, valid && (b == b0));
    if (uni) {
        #pragma unroll
        for (int c2 = 0; c2 < NCLS; c2++) {
            float v = y[c2];
            #pragma unroll
            for (int off = 16; off; off >>= 1)
                v += __shfl_xor_sync(mask, v, off);
            if ((t & 31) == 0) atomicAdd(&out[b0 * NCLS + c2], v);
        }
    } else if (valid) {
        #pragma unroll
        for (int c2 = 0; c2 < NCLS; c2++)
            atomicAdd(&out[b * NCLS + c2], y[c2]);
    }
}

// ---------------- launch ---------------------------------------------------
extern "C" void kernel_launch(void* const* d_in, const int* in_sizes, int n_in,
                              void* d_out, int out_size) {
    const float* x     = (const float*)d_in[0];
    const int*   ei    = (const int*)d_in[1];     // int32
    const int*   batch = (const int*)d_in[2];     // int32
    const float* W1  = (const float*)d_in[3];
    const float* as1 = (const float*)d_in[4];
    const float* ad1 = (const float*)d_in[5];
    const float* b1  = (const float*)d_in[6];
    const float* W2  = (const float*)d_in[7];
    const float* as2 = (const float*)d_in[8];
    const float* ad2 = (const float*)d_in[9];
    const float* b2  = (const float*)d_in[10];
    const float* mw1 = (const float*)d_in[11];
    const float* mb1 = (const float*)d_in[12];
    const float* mw2 = (const float*)d_in[13];
    const float* mb2 = (const float*)d_in[14];
    float* out = (float*)d_out;

    const int TB = 256;
    int gridE = (NEDGES + TB - 1) / TB;
    int gridN = (NNODES + TB - 1) / TB;
    int gridG = (NNODES + 63) / 64;           // 1563
    int gridC = (NNODES * 32 + TB - 1) / TB;  // warp per node

    // CSR build (once, reused by both convs)
    k_init_deg<<<gridN, TB>>>();
    k_deg<<<gridE, TB>>>(ei);
    k_scan1<<<NBLK, SCHUNK>>>();
    k_scan2<<<1, 512>>>();
    k_scan3<<<NBLK, SCHUNK>>>();
    k_scatter<<<gridE, TB>>>(ei);

    // conv 1
    k_gemm_attn<0><<<gridG, TB>>>(x, W1, as1, ad1);
    k_conv<<<gridC, TB>>>(b1);

    // conv 2
    k_gemm_attn<1><<<gridG, TB>>>(nullptr, W2, as2, ad2);
    k_conv<<<gridC, TB>>>(b2);

    // MLP + pool
    k_zero<<<(NGRAPH * NCLS + TB - 1) / TB, TB>>>(out);
    k_mlp_pool<<<gridN, TB>>>(mw1, mb1, mw2, mb2, batch, out);
}

// round 8
// speedup vs baseline: 1.7862x; 1.0013x over previous
#include <cuda_runtime.h>
#include <math_constants.h>

#define NNODES 100000
#define NEDGES 1600000
#define EP     (NEDGES + NNODES)   // edges + self loops
#define HD     64
#define NCLS   10
#define NGRAPH 128

#define SCHUNK 256
#define NBLK   ((NNODES + SCHUNK - 1) / SCHUNK)   // 391

// ---------------- scratch (device globals; no allocations) ----------------
__device__ __align__(16) float g_hbuf[NNODES * HD];   // h = in @ W
__device__ __align__(16) float g_abuf[NNODES * HD];   // conv input / output
__device__ float g_als[NNODES];
__device__ float g_ald[NNODES];
__device__ int   g_deg[NNODES];
__device__ int   g_rowptr[NNODES + 1];
__device__ int   g_cursor[NNODES];
__device__ int   g_csr_src[EP];
__device__ int   g_blk_incl[NBLK];     // -1 = not ready; >=0 = block inclusive total

__device__ __forceinline__ float eluf(float x) {
    return x > 0.f ? x : expm1f(x);
}

// ---------------- CSR build ------------------------------------------------
__global__ void k_init() {
    int i = blockIdx.x * blockDim.x + threadIdx.x;
    if (i < NNODES) g_deg[i] = 0;
    if (i < NBLK)   g_blk_incl[i] = -1;
}

// edge_index is INT32 (JAX x64 disabled downgrades jnp.int64 -> int32)
__global__ void k_deg(const int* __restrict__ ei) {
    int i = blockIdx.x * blockDim.x + threadIdx.x;
    if (i < NEDGES) atomicAdd(&g_deg[ei[NEDGES + i]], 1);
}

// single-kernel scan with decoupled lookback. All NBLK blocks are resident
// simultaneously (100K threads << chip capacity) so spinning is safe.
__global__ __launch_bounds__(SCHUNK) void k_scan() {
    __shared__ int sh[SCHUNK];
    __shared__ int s_off;
    const unsigned FULL = 0xffffffffu;
    int t = threadIdx.x, b = blockIdx.x;
    int idx = b * SCHUNK + t;
    int v = (idx < NNODES) ? g_deg[idx] + 1 : 0;   // +1 = self loop

    sh[t] = v;
    __syncthreads();
    for (int off = 1; off < SCHUNK; off <<= 1) {
        int x = (t >= off) ? sh[t - off] : 0;
        __syncthreads();
        sh[t] += x;
        __syncthreads();
    }
    int incl = sh[t];
    if (t == SCHUNK - 1)
        atomicExch(&g_blk_incl[b], incl);          // publish block total

    if (t < 32) {
        int sum = 0;
        for (int p = t; p < b; p += 32) {
            int a;
            do { a = atomicAdd(&g_blk_incl[p], 0); } while (a < 0);
            sum += a;
        }
        #pragma unroll
        for (int off = 16; off; off >>= 1)
            sum += __shfl_xor_sync(FULL, sum, off);
        if (t == 0) s_off = sum;
    }
    __syncthreads();

    if (idx < NNODES) {
        int rp = s_off + incl - v;                 // exclusive prefix
        g_rowptr[idx] = rp;
        g_csr_src[rp] = idx;                       // self loop at slot 0
        g_cursor[idx] = rp + 1;
        if (idx == NNODES - 1) g_rowptr[NNODES] = rp + v;   // == EP
    }
}

__global__ void k_scatter(const int* __restrict__ ei) {
    int e = blockIdx.x * blockDim.x + threadIdx.x;
    if (e >= NEDGES) return;
    int d = ei[NEDGES + e];
    int pos = atomicAdd(&g_cursor[d], 1);
    g_csr_src[pos] = ei[e];
}

// ---------------- GEMM + attention coefs (register-blocked 4x4) ------------
template <int LAYER>
__global__ __launch_bounds__(256) void k_gemm_attn(
    const float* __restrict__ xin,
    const float* __restrict__ W,
    const float* __restrict__ a_s,
    const float* __restrict__ a_d)
{
    __shared__ __align__(16) float Ws[64 * 68];
    __shared__ __align__(16) float xs[64 * 68];

    int t = threadIdx.x;
    int base = blockIdx.x * 64;

    for (int i = t; i < 1024; i += 256) {
        float4 w = *(const float4*)(W + i * 4);
        *(float4*)&Ws[(i >> 4) * 68 + (i & 15) * 4] = w;
    }
    for (int i = t; i < 1024; i += 256) {
        int row = i >> 4, c4 = i & 15;
        int grow = base + row;
        float4 v = make_float4(0.f, 0.f, 0.f, 0.f);
        if (grow < NNODES) {
            if (LAYER == 0) {
                v = *(const float4*)(xin + grow * 64 + c4 * 4);
            } else {
                float4 u = *(const float4*)&g_abuf[grow * 64 + c4 * 4];
                v = make_float4(eluf(u.x), eluf(u.y), eluf(u.z), eluf(u.w));
            }
        }
        *(float4*)&xs[row * 68 + c4 * 4] = v;
    }
    __syncthreads();

    int c  = t & 15;
    int rq = t >> 4;
    int j0 = c * 4;
    int rbase = rq * 4;

    float4 acc0 = make_float4(0.f,0.f,0.f,0.f);
    float4 acc1 = acc0, acc2 = acc0, acc3 = acc0;

    #pragma unroll 8
    for (int k = 0; k < 64; k++) {
        float4 w  = *(const float4*)&Ws[k * 68 + j0];
        float x0 = xs[(rbase + 0) * 68 + k];
        float x1 = xs[(rbase + 1) * 68 + k];
        float x2 = xs[(rbase + 2) * 68 + k];
        float x3 = xs[(rbase + 3) * 68 + k];
        acc0.x += x0 * w.x; acc0.y += x0 * w.y; acc0.z += x0 * w.z; acc0.w += x0 * w.w;
        acc1.x += x1 * w.x; acc1.y += x1 * w.y; acc1.z += x1 * w.z; acc1.w += x1 * w.w;
        acc2.x += x2 * w.x; acc2.y += x2 * w.y; acc2.z += x2 * w.z; acc2.w += x2 * w.w;
        acc3.x += x3 * w.x; acc3.y += x3 * w.y; acc3.z += x3 * w.z; acc3.w += x3 * w.w;
    }

    float4 asv = *(const float4*)(a_s + j0);
    float4 adv = *(const float4*)(a_d + j0);

    float4 accs[4] = {acc0, acc1, acc2, acc3};
    #pragma unroll
    for (int i = 0; i < 4; i++) {
        int row = base + rbase + i;
        float4 a = accs[i];
        if (row < NNODES)
            *(float4*)&g_hbuf[row * 64 + j0] = a;
        float ps = a.x * asv.x + a.y * asv.y + a.z * asv.z + a.w * asv.w;
        float pd = a.x * adv.x + a.y * adv.y + a.z * adv.z + a.w * adv.w;
        #pragma unroll
        for (int off = 8; off; off >>= 1) {
            ps += __shfl_xor_sync(0xffffffffu, ps, off);
            pd += __shfl_xor_sync(0xffffffffu, pd, off);
        }
        if (c == 0 && row < NNODES) {
            g_als[row] = ps;
            g_ald[row] = pd;
        }
    }
}

// ---------------- fused conv: shift-free softmax + aggregate ---------------
// Paired lanes: lanes 0-15 handle even edge of a pair, 16-31 the odd edge.
// Per 2 edges/lane: 2 SHFL + 1 LDG.128 + 4 FFMA. Pair halves merged at end.
__global__ __launch_bounds__(256) void k_conv(const float* __restrict__ bias) {
    const unsigned FULL = 0xffffffffu;
    int wid  = (blockIdx.x * 256 + threadIdx.x) >> 5;
    int lane = threadIdx.x & 31;
    if (wid >= NNODES) return;
    int pair = lane >> 4;
    int wi   = lane & 15;

    int r0 = g_rowptr[wid];
    int r1 = g_rowptr[wid + 1];
    float ald_d = g_ald[wid];

    float4 acc = make_float4(0.f, 0.f, 0.f, 0.f);
    float denp = 0.f;

    for (int cb = r0; cb < r1; cb += 32) {
        int e = cb + lane;
        int   s  = 0;
        float ex = 0.f;
        if (e < r1) {
            s = g_csr_src[e];
            float sc = g_als[s] + ald_d;
            sc = sc > 0.f ? sc : 0.2f * sc;       // leaky relu
            ex = __expf(fminf(sc, 75.f));         // overflow guard (never hit)
        }
        denp += ex;
        int cl = (r1 - cb) < 32 ? (r1 - cb) : 32;
        int j = 0;
        #pragma unroll 4
        for (; j + 2 <= cl; j += 2) {
            int jj = j + pair;
            int   sj  = __shfl_sync(FULL, s, jj);
            float exj = __shfl_sync(FULL, ex, jj);
            float4 hv = *(const float4*)&g_hbuf[sj * 64 + wi * 4];
            acc.x += exj * hv.x; acc.y += exj * hv.y;
            acc.z += exj * hv.z; acc.w += exj * hv.w;
        }
        if (j < cl) {   // odd remainder: single edge, half-warp gathers it
            int   sj  = __shfl_sync(FULL, s, j);
            float exj = __shfl_sync(FULL, ex, j);
            if (pair == 0) {
                float4 hv = *(const float4*)&g_hbuf[sj * 64 + wi * 4];
                acc.x += exj * hv.x; acc.y += exj * hv.y;
                acc.z += exj * hv.z; acc.w += exj * hv.w;
            }
        }
    }

    // merge the two pair-halves (same features, disjoint edge subsets)
    acc.x += __shfl_xor_sync(FULL, acc.x, 16);
    acc.y += __shfl_xor_sync(FULL, acc.y, 16);
    acc.z += __shfl_xor_sync(FULL, acc.z, 16);
    acc.w += __shfl_xor_sync(FULL, acc.w, 16);

    float den = denp;
    #pragma unroll
    for (int off = 16; off; off >>= 1)
        den += __shfl_xor_sync(FULL, den, off);

    if (pair == 0) {
        float inv = 1.f / den;
        float4 bv = *(const float4*)(bias + wi * 4);
        float4 o;
        o.x = acc.x * inv + bv.x;
        o.y = acc.y * inv + bv.y;
        o.z = acc.z * inv + bv.z;
        o.w = acc.w * inv + bv.w;
        *(float4*)&g_abuf[wid * 64 + wi * 4] = o;
    }
}

// ---------------- zero the pooled output ----------------------------------
__global__ void k_zero(float* out) {
    int i = blockIdx.x * blockDim.x + threadIdx.x;
    if (i < NGRAPH * NCLS) out[i] = 0.f;
}

// ---------------- MLP head + global_add_pool ------------------------------
__global__ __launch_bounds__(256) void k_mlp_pool(
    const float* __restrict__ mw1, const float* __restrict__ mb1,
    const float* __restrict__ mw2, const float* __restrict__ mb2,
    const int* __restrict__ batch, float* __restrict__ out)
{
    __shared__ __align__(16) float W1s[64 * 68];
    __shared__ float W2s[64 * 12];
    __shared__ float b1s[64];
    __shared__ float b2s[NCLS];

    int t = threadIdx.x;
    for (int i = t; i < 64 * 64; i += 256)
        W1s[(i >> 6) * 68 + (i & 63)] = mw1[i];
    for (int i = t; i < 64 * NCLS; i += 256)
        W2s[(i / NCLS) * 12 + (i % NCLS)] = mw2[i];
    if (t < 64)   b1s[t] = mb1[t];
    if (t < NCLS) b2s[t] = mb2[t];
    __syncthreads();

    int node = blockIdx.x * blockDim.x + t;
    bool valid = node < NNODES;

    float z[64];
    #pragma unroll
    for (int j = 0; j < 64; j++) z[j] = 0.f;

    int b = 0;
    if (valid) {
        b = batch[node];
        #pragma unroll
        for (int k4 = 0; k4 < 16; k4++) {
            float4 xv4 = *(const float4*)&g_abuf[node * 64 + k4 * 4];
            float xv[4] = {xv4.x, xv4.y, xv4.z, xv4.w};
            #pragma unroll
            for (int kk = 0; kk < 4; kk++) {
                float xk = eluf(xv[kk]);
                int k = k4 * 4 + kk;
                #pragma unroll
                for (int j = 0; j < 64; j += 4) {
                    float4 w = *(const float4*)&W1s[k * 68 + j];
                    z[j]     += xk * w.x;
                    z[j + 1] += xk * w.y;
                    z[j + 2] += xk * w.z;
                    z[j + 3] += xk * w.w;
                }
            }
        }
    }

    float y[NCLS];
    #pragma unroll
    for (int c2 = 0; c2 < NCLS; c2++) y[c2] = valid ? b2s[c2] : 0.f;

    if (valid) {
        #pragma unroll
        for (int j = 0; j < 64; j++) {
            float zj = z[j] + b1s[j];
            zj = zj > 0.f ? zj : 0.f;
            #pragma unroll
            for (int c2 = 0; c2 < NCLS; c2++)
                y[c2] += zj * W2s[j * 12 + c2];
        }
    }

    unsigned mask = 0xffffffffu;
    int b0 = __shfl_sync(mask, b, 0);
    bool uni = __all_sync(mask, valid && (b == b0));
    if (uni) {
        #pragma unroll
        for (int c2 = 0; c2 < NCLS; c2++) {
            float v = y[c2];
            #pragma unroll
            for (int off = 16; off; off >>= 1)
                v += __shfl_xor_sync(mask, v, off);
            if ((t & 31) == 0) atomicAdd(&out[b0 * NCLS + c2], v);
        }
    } else if (valid) {
        #pragma unroll
        for (int c2 = 0; c2 < NCLS; c2++)
            atomicAdd(&out[b * NCLS + c2], y[c2]);
    }
}

// ---------------- launch ---------------------------------------------------
extern "C" void kernel_launch(void* const* d_in, const int* in_sizes, int n_in,
                              void* d_out, int out_size) {
    const float* x     = (const float*)d_in[0];
    const int*   ei    = (const int*)d_in[1];     // int32
    const int*   batch = (const int*)d_in[2];     // int32
    const float* W1  = (const float*)d_in[3];
    const float* as1 = (const float*)d_in[4];
    const float* ad1 = (const float*)d_in[5];
    const float* b1  = (const float*)d_in[6];
    const float* W2  = (const float*)d_in[7];
    const float* as2 = (const float*)d_in[8];
    const float* ad2 = (const float*)d_in[9];
    const float* b2  = (const float*)d_in[10];
    const float* mw1 = (const float*)d_in[11];
    const float* mb1 = (const float*)d_in[12];
    const float* mw2 = (const float*)d_in[13];
    const float* mb2 = (const float*)d_in[14];
    float* out = (float*)d_out;

    // one side stream + fork/join events (created once; host objects only)
    static cudaStream_t s2 = nullptr;
    static cudaEvent_t  eF = nullptr, eJ = nullptr;
    if (!s2) {
        cudaStreamCreateWithFlags(&s2, cudaStreamNonBlocking);
        cudaEventCreateWithFlags(&eF, cudaEventDisableTiming);
        cudaEventCreateWithFlags(&eJ, cudaEventDisableTiming);
    }

    const int TB = 256;
    int gridE = (NEDGES + TB - 1) / TB;
    int gridN = (NNODES + TB - 1) / TB;
    int gridG = (NNODES + 63) / 64;
    int gridC = (NNODES * 32 + TB - 1) / TB;  // warp per node

    // fork: side stream runs GEMM-1 + out-zero while stream 0 builds CSR
    cudaEventRecord(eF, 0);
    cudaStreamWaitEvent(s2, eF, 0);

    // stream 0: CSR build
    k_init<<<gridN, TB>>>();
    k_deg<<<gridE, TB>>>(ei);
    k_scan<<<NBLK, SCHUNK>>>();
    k_scatter<<<gridE, TB>>>(ei);

    // side stream: GEMM-1 (independent of CSR) + output zeroing
    k_gemm_attn<0><<<gridG, TB, 0, s2>>>(x, W1, as1, ad1);
    k_zero<<<(NGRAPH * NCLS + TB - 1) / TB, TB, 0, s2>>>(out);

    // join
    cudaEventRecord(eJ, s2);
    cudaStreamWaitEvent(0, eJ, 0);

    // conv 1
    k_conv<<<gridC, TB>>>(b1);

    // conv 2
    k_gemm_attn<1><<<gridG, TB>>>(nullptr, W2, as2, ad2);
    k_conv<<<gridC, TB>>>(b2);

    // MLP + pool
    k_mlp_pool<<<gridN, TB>>>(mw1, mb1, mw2, mb2, batch, out);
}

// round 9
// speedup vs baseline: 1.9180x; 1.0738x over previous
#include <cuda_runtime.h>
#include <cuda_fp16.h>
#include <math_constants.h>

#define NNODES 100000
#define NEDGES 1600000
#define EP     (NEDGES + NNODES)   // edges + self loops
#define HD     64
#define NCLS   10
#define NGRAPH 128

#define SCHUNK 256
#define NBLK   ((NNODES + SCHUNK - 1) / SCHUNK)   // 391

// ---------------- scratch (device globals; no allocations) ----------------
__device__ __align__(16) __half2 g_h16[NNODES * 32];  // h rows, fp16 payload (128B/row)
__device__ __align__(16) float g_abuf[NNODES * HD];   // conv input / output (fp32)
__device__ float g_als[NNODES];
__device__ float g_ald[NNODES];
__device__ int   g_deg[NNODES];
__device__ int   g_rowptr[NNODES + 1];
__device__ int   g_cursor[NNODES];
__device__ int   g_csr_src[EP];
__device__ int   g_blk_incl[NBLK];     // -1 = not ready; >=0 = block inclusive total

__device__ __forceinline__ float eluf(float x) {
    return x > 0.f ? x : expm1f(x);
}

// ---------------- CSR build ------------------------------------------------
__global__ void k_init(float* __restrict__ out) {
    int i = blockIdx.x * blockDim.x + threadIdx.x;
    if (i < NNODES) g_deg[i] = 0;
    if (i < NBLK)   g_blk_incl[i] = -1;
    if (i < NGRAPH * NCLS) out[i] = 0.f;
}

// edge_index is INT32 (JAX x64 disabled downgrades jnp.int64 -> int32)
// 4 edges per thread: 1 int4 load + 4 independent atomics (MLP=4).
__global__ void k_deg(const int* __restrict__ ei) {
    int i = (blockIdx.x * blockDim.x + threadIdx.x) * 4;
    if (i >= NEDGES) return;
    int4 d = *(const int4*)(ei + NEDGES + i);     // NEDGES %4==0 -> aligned
    atomicAdd(&g_deg[d.x], 1);
    atomicAdd(&g_deg[d.y], 1);
    atomicAdd(&g_deg[d.z], 1);
    atomicAdd(&g_deg[d.w], 1);
}

// single-kernel scan with decoupled lookback (all NBLK blocks resident).
__global__ __launch_bounds__(SCHUNK) void k_scan() {
    __shared__ int sh[SCHUNK];
    __shared__ int s_off;
    const unsigned FULL = 0xffffffffu;
    int t = threadIdx.x, b = blockIdx.x;
    int idx = b * SCHUNK + t;
    int v = (idx < NNODES) ? g_deg[idx] + 1 : 0;   // +1 = self loop

    sh[t] = v;
    __syncthreads();
    for (int off = 1; off < SCHUNK; off <<= 1) {
        int x = (t >= off) ? sh[t - off] : 0;
        __syncthreads();
        sh[t] += x;
        __syncthreads();
    }
    int incl = sh[t];
    if (t == SCHUNK - 1)
        atomicExch(&g_blk_incl[b], incl);

    if (t < 32) {
        int sum = 0;
        for (int p = t; p < b; p += 32) {
            int a;
            do { a = atomicAdd(&g_blk_incl[p], 0); } while (a < 0);
            sum += a;
        }
        #pragma unroll
        for (int off = 16; off; off >>= 1)
            sum += __shfl_xor_sync(FULL, sum, off);
        if (t == 0) s_off = sum;
    }
    __syncthreads();

    if (idx < NNODES) {
        int rp = s_off + incl - v;
        g_rowptr[idx] = rp;
        g_csr_src[rp] = idx;                       // self loop at slot 0
        g_cursor[idx] = rp + 1;
        if (idx == NNODES - 1) g_rowptr[NNODES] = rp + v;   // == EP
    }
}

// 4 edges per thread: int4 src + int4 dst, 4 independent atomic chains.
__global__ void k_scatter(const int* __restrict__ ei) {
    int i = (blockIdx.x * blockDim.x + threadIdx.x) * 4;
    if (i >= NEDGES) return;
    int4 s = *(const int4*)(ei + i);
    int4 d = *(const int4*)(ei + NEDGES + i);
    int p0 = atomicAdd(&g_cursor[d.x], 1);
    int p1 = atomicAdd(&g_cursor[d.y], 1);
    int p2 = atomicAdd(&g_cursor[d.z], 1);
    int p3 = atomicAdd(&g_cursor[d.w], 1);
    g_csr_src[p0] = s.x;
    g_csr_src[p1] = s.y;
    g_csr_src[p2] = s.z;
    g_csr_src[p3] = s.w;
}

// ---------------- GEMM + attention coefs (register-blocked 4x4) ------------
// h written as fp16 half2 rows (conv gather payload); attention logits from
// the fp32 accumulators, conv output stays fp32 -> only the gather is fp16.
template <int LAYER>
__global__ __launch_bounds__(256) void k_gemm_attn(
    const float* __restrict__ xin,
    const float* __restrict__ W,
    const float* __restrict__ a_s,
    const float* __restrict__ a_d)
{
    __shared__ __align__(16) float Ws[64 * 68];
    __shared__ __align__(16) float xs[64 * 68];

    int t = threadIdx.x;
    int base = blockIdx.x * 64;

    for (int i = t; i < 1024; i += 256) {
        float4 w = *(const float4*)(W + i * 4);
        *(float4*)&Ws[(i >> 4) * 68 + (i & 15) * 4] = w;
    }
    for (int i = t; i < 1024; i += 256) {
        int row = i >> 4, c4 = i & 15;
        int grow = base + row;
        float4 v = make_float4(0.f, 0.f, 0.f, 0.f);
        if (grow < NNODES) {
            if (LAYER == 0) {
                v = *(const float4*)(xin + grow * 64 + c4 * 4);
            } else {
                float4 u = *(const float4*)&g_abuf[grow * 64 + c4 * 4];
                v = make_float4(eluf(u.x), eluf(u.y), eluf(u.z), eluf(u.w));
            }
        }
        *(float4*)&xs[row * 68 + c4 * 4] = v;
    }
    __syncthreads();

    int c  = t & 15;
    int rq = t >> 4;
    int j0 = c * 4;
    int rbase = rq * 4;

    float4 acc0 = make_float4(0.f,0.f,0.f,0.f);
    float4 acc1 = acc0, acc2 = acc0, acc3 = acc0;

    #pragma unroll 8
    for (int k = 0; k < 64; k++) {
        float4 w  = *(const float4*)&Ws[k * 68 + j0];
        float x0 = xs[(rbase + 0) * 68 + k];
        float x1 = xs[(rbase + 1) * 68 + k];
        float x2 = xs[(rbase + 2) * 68 + k];
        float x3 = xs[(rbase + 3) * 68 + k];
        acc0.x += x0 * w.x; acc0.y += x0 * w.y; acc0.z += x0 * w.z; acc0.w += x0 * w.w;
        acc1.x += x1 * w.x; acc1.y += x1 * w.y; acc1.z += x1 * w.z; acc1.w += x1 * w.w;
        acc2.x += x2 * w.x; acc2.y += x2 * w.y; acc2.z += x2 * w.z; acc2.w += x2 * w.w;
        acc3.x += x3 * w.x; acc3.y += x3 * w.y; acc3.z += x3 * w.z; acc3.w += x3 * w.w;
    }

    float4 asv = *(const float4*)(a_s + j0);
    float4 adv = *(const float4*)(a_d + j0);

    float4 accs[4] = {acc0, acc1, acc2, acc3};
    #pragma unroll
    for (int i = 0; i < 4; i++) {
        int row = base + rbase + i;
        float4 a = accs[i];
        if (row < NNODES) {
            __half2 p0 = __floats2half2_rn(a.x, a.y);
            __half2 p1 = __floats2half2_rn(a.z, a.w);
            uint2 pk;
            pk.x = *(unsigned*)&p0;
            pk.y = *(unsigned*)&p1;
            *(uint2*)&g_h16[row * 32 + c * 2] = pk;
        }
        float ps = a.x * asv.x + a.y * asv.y + a.z * asv.z + a.w * asv.w;
        float pd = a.x * adv.x + a.y * adv.y + a.z * adv.z + a.w * adv.w;
        #pragma unroll
        for (int off = 8; off; off >>= 1) {
            ps += __shfl_xor_sync(0xffffffffu, ps, off);
            pd += __shfl_xor_sync(0xffffffffu, pd, off);
        }
        if (c == 0 && row < NNODES) {
            g_als[row] = ps;
            g_ald[row] = pd;
        }
    }
}

// ---------------- fused conv: shift-free softmax + fp16 gather -------------
// Paired lanes: 16 lanes per edge x 8B (4 halves) = 128B = ONE L2 line/edge.
__global__ __launch_bounds__(256) void k_conv(const float* __restrict__ bias) {
    const unsigned FULL = 0xffffffffu;
    int wid  = (blockIdx.x * 256 + threadIdx.x) >> 5;
    int lane = threadIdx.x & 31;
    if (wid >= NNODES) return;
    int pair = lane >> 4;
    int wi   = lane & 15;

    int r0 = g_rowptr[wid];
    int r1 = g_rowptr[wid + 1];
    float ald_d = g_ald[wid];

    float4 acc = make_float4(0.f, 0.f, 0.f, 0.f);
    float denp = 0.f;

    for (int cb = r0; cb < r1; cb += 32) {
        int e = cb + lane;
        int   s  = 0;
        float ex = 0.f;
        if (e < r1) {
            s = g_csr_src[e];
            float sc = g_als[s] + ald_d;
            sc = sc > 0.f ? sc : 0.2f * sc;       // leaky relu
            ex = __expf(fminf(sc, 75.f));         // overflow guard (never hit)
        }
        denp += ex;
        int cl = (r1 - cb) < 32 ? (r1 - cb) : 32;
        int j = 0;
        #pragma unroll 4
        for (; j + 2 <= cl; j += 2) {
            int jj = j + pair;
            int   sj  = __shfl_sync(FULL, s, jj);
            float exj = __shfl_sync(FULL, ex, jj);
            uint2 pk = *(const uint2*)&g_h16[sj * 32 + wi * 2];
            float2 f0 = __half22float2(*(__half2*)&pk.x);
            float2 f1 = __half22float2(*(__half2*)&pk.y);
            acc.x += exj * f0.x; acc.y += exj * f0.y;
            acc.z += exj * f1.x; acc.w += exj * f1.y;
        }
        if (j < cl) {   // odd remainder: half-warp gathers the single edge
            int   sj  = __shfl_sync(FULL, s, j);
            float exj = __shfl_sync(FULL, ex, j);
            if (pair == 0) {
                uint2 pk = *(const uint2*)&g_h16[sj * 32 + wi * 2];
                float2 f0 = __half22float2(*(__half2*)&pk.x);
                float2 f1 = __half22float2(*(__half2*)&pk.y);
                acc.x += exj * f0.x; acc.y += exj * f0.y;
                acc.z += exj * f1.x; acc.w += exj * f1.y;
            }
        }
    }

    acc.x += __shfl_xor_sync(FULL, acc.x, 16);
    acc.y += __shfl_xor_sync(FULL, acc.y, 16);
    acc.z += __shfl_xor_sync(FULL, acc.z, 16);
    acc.w += __shfl_xor_sync(FULL, acc.w, 16);

    float den = denp;
    #pragma unroll
    for (int off = 16; off; off >>= 1)
        den += __shfl_xor_sync(FULL, den, off);

    if (pair == 0) {
        float inv = 1.f / den;
        float4 bv = *(const float4*)(bias + wi * 4);
        float4 o;
        o.x = acc.x * inv + bv.x;
        o.y = acc.y * inv + bv.y;
        o.z = acc.z * inv + bv.z;
        o.w = acc.w * inv + bv.w;
        *(float4*)&g_abuf[wid * 64 + wi * 4] = o;
    }
}

// ---------------- MLP head + global_add_pool ------------------------------
__global__ __launch_bounds__(256) void k_mlp_pool(
    const float* __restrict__ mw1, const float* __restrict__ mb1,
    const float* __restrict__ mw2, const float* __restrict__ mb2,
    const int* __restrict__ batch, float* __restrict__ out)
{
    __shared__ __align__(16) float W1s[64 * 68];
    __shared__ float W2s[64 * 12];
    __shared__ float b1s[64];
    __shared__ float b2s[NCLS];

    int t = threadIdx.x;
    for (int i = t; i < 64 * 64; i += 256)
        W1s[(i >> 6) * 68 + (i & 63)] = mw1[i];
    for (int i = t; i < 64 * NCLS; i += 256)
        W2s[(i / NCLS) * 12 + (i % NCLS)] = mw2[i];
    if (t < 64)   b1s[t] = mb1[t];
    if (t < NCLS) b2s[t] = mb2[t];
    __syncthreads();

    int node = blockIdx.x * blockDim.x + t;
    bool valid = node < NNODES;

    float z[64];
    #pragma unroll
    for (int j = 0; j < 64; j++) z[j] = 0.f;

    int b = 0;
    if (valid) {
        b = batch[node];
        #pragma unroll
        for (int k4 = 0; k4 < 16; k4++) {
            float4 xv4 = *(const float4*)&g_abuf[node * 64 + k4 * 4];
            float xv[4] = {xv4.x, xv4.y, xv4.z, xv4.w};
            #pragma unroll
            for (int kk = 0; kk < 4; kk++) {
                float xk = eluf(xv[kk]);
                int k = k4 * 4 + kk;
                #pragma unroll
                for (int j = 0; j < 64; j += 4) {
                    float4 w = *(const float4*)&W1s[k * 68 + j];
                    z[j]     += xk * w.x;
                    z[j + 1] += xk * w.y;
                    z[j + 2] += xk * w.z;
                    z[j + 3] += xk * w.w;
                }
            }
        }
    }

    float y[NCLS];
    #pragma unroll
    for (int c2 = 0; c2 < NCLS; c2++) y[c2] = valid ? b2s[c2] : 0.f;

    if (valid) {
        #pragma unroll
        for (int j = 0; j < 64; j++) {
            float zj = z[j] + b1s[j];
            zj = zj > 0.f ? zj : 0.f;
            #pragma unroll
            for (int c2 = 0; c2 < NCLS; c2++)
                y[c2] += zj * W2s[j * 12 + c2];
        }
    }

    unsigned mask = 0xffffffffu;
    int b0 = __shfl_sync(mask, b, 0);
    bool uni = __all_sync(mask, valid && (b == b0));
    if (uni) {
        #pragma unroll
        for (int c2 = 0; c2 < NCLS; c2++) {
            float v = y[c2];
            #pragma unroll
            for (int off = 16; off; off >>= 1)
                v += __shfl_xor_sync(mask, v, off);
            if ((t & 31) == 0) atomicAdd(&out[b0 * NCLS + c2], v);
        }
    } else if (valid) {
        #pragma unroll
        for (int c2 = 0; c2 < NCLS; c2++)
            atomicAdd(&out[b * NCLS + c2], y[c2]);
    }
}

// ---------------- launch ---------------------------------------------------
extern "C" void kernel_launch(void* const* d_in, const int* in_sizes, int n_in,
                              void* d_out, int out_size) {
    const float* x     = (const float*)d_in[0];
    const int*   ei    = (const int*)d_in[1];     // int32
    const int*   batch = (const int*)d_in[2];     // int32
    const float* W1  = (const float*)d_in[3];
    const float* as1 = (const float*)d_in[4];
    const float* ad1 = (const float*)d_in[5];
    const float* b1  = (const float*)d_in[6];
    const float* W2  = (const float*)d_in[7];
    const float* as2 = (const float*)d_in[8];
    const float* ad2 = (const float*)d_in[9];
    const float* b2  = (const float*)d_in[10];
    const float* mw1 = (const float*)d_in[11];
    const float* mb1 = (const float*)d_in[12];
    const float* mw2 = (const float*)d_in[13];
    const float* mb2 = (const float*)d_in[14];
    float* out = (float*)d_out;

    static cudaStream_t s2 = nullptr;
    static cudaEvent_t  eF = nullptr, eJ = nullptr;
    if (!s2) {
        cudaStreamCreateWithFlags(&s2, cudaStreamNonBlocking);
        cudaEventCreateWithFlags(&eF, cudaEventDisableTiming);
        cudaEventCreateWithFlags(&eJ, cudaEventDisableTiming);
    }

    const int TB = 256;
    int gridE4 = (NEDGES / 4 + TB - 1) / TB;      // NEDGES % 4 == 0
    int gridN  = (NNODES + TB - 1) / TB;
    int gridG  = (NNODES + 63) / 64;
    int gridC  = (NNODES * 32 + TB - 1) / TB;     // warp per node

    // fork: side stream runs GEMM-1 while stream 0 builds CSR
    cudaEventRecord(eF, 0);
    cudaStreamWaitEvent(s2, eF, 0);

    // stream 0: CSR build (+ zero out inside k_init)
    k_init<<<gridN, TB>>>(out);
    k_deg<<<gridE4, TB>>>(ei);
    k_scan<<<NBLK, SCHUNK>>>();
    k_scatter<<<gridE4, TB>>>(ei);

    // side stream: GEMM-1 (independent of CSR)
    k_gemm_attn<0><<<gridG, TB, 0, s2>>>(x, W1, as1, ad1);

    // join
    cudaEventRecord(eJ, s2);
    cudaStreamWaitEvent(0, eJ, 0);

    // conv 1
    k_conv<<<gridC, TB>>>(b1);

    // conv 2
    k_gemm_attn<1><<<gridG, TB>>>(nullptr, W2, as2, ad2);
    k_conv<<<gridC, TB>>>(b2);

    // MLP + pool
    k_mlp_pool<<<gridN, TB>>>(mw1, mb1, mw2, mb2, batch, out);
}